// round 11
// baseline (speedup 1.0000x reference)
#include <cuda_runtime.h>
#include <cuda_fp16.h>
#include <stdint.h>
#include <math.h>

// ----------------------------------------------------------------------------
// FARGAN vocoder. Round 9: 8-CTA clusters, 4 batch rows per cluster
// (16 clusters x 8 = 128 CTAs). Each CTA computes 1/8 of every stage's
// outputs for all 4 rows -> chip weight traffic 72 MB/subframe. GRU gates
// permuted so each rank owns full (r,z,n) triplets for its 32 states.
// fp16 K-major weights, fp32 accumulate, 1024 threads/CTA.
// ALL working arrays live in dynamic SMEM (static limit is 48 KB).
// ----------------------------------------------------------------------------

#define NFRAMES 100
#define NB      64
#define NTHREADS 1024
#define NROWS   4     // rows per cluster
#define CLSZ    8     // CTAs per cluster

__device__ __forceinline__ float sigmoidf_(float x) { return 1.0f / (1.0f + expf(-x)); }

__device__ __forceinline__ uint32_t s2u_(const void* p) {
  uint32_t a;
  asm("{ .reg .u64 t; cvta.to.shared.u64 t, %1; cvt.u32.u64 %0, t; }" : "=r"(a) : "l"(p));
  return a;
}
__device__ __forceinline__ uint32_t mapa_u_(uint32_t a, uint32_t r) {
  uint32_t d;
  asm("mapa.shared::cluster.u32 %0, %1, %2;" : "=r"(d) : "r"(a), "r"(r));
  return d;
}
__device__ __forceinline__ void st_peer_(uint32_t a, float v) {
  asm volatile("st.shared::cluster.f32 [%0], %1;" :: "r"(a), "f"(v));
}
#define CLUSTER_SYNC_() do { \
  asm volatile("barrier.cluster.arrive.aligned;" ::: "memory"); \
  asm volatile("barrier.cluster.wait.aligned;" ::: "memory"); \
} while (0)

// fp16 weights, 8 rank-slices per matrix: [8][Kpad][Oo]
enum : int {
  OFFH_FW      = 0,                          // 8 x 544 x 32
  OFFH_FWGLU   = OFFH_FW      + 544 * 256,   // 8 x 256 x 32
  OFFH_G1IH    = OFFH_FWGLU   + 256 * 256,   // 8 x 384 x 96
  OFFH_G1HH    = OFFH_G1IH    + 384 * 768,   // 8 x 256 x 96
  OFFH_G2IH    = OFFH_G1HH    + 256 * 768,
  OFFH_G2HH    = OFFH_G2IH    + 384 * 768,
  OFFH_G3IH    = OFFH_G2HH    + 256 * 768,
  OFFH_G3HH    = OFFH_G3IH    + 384 * 768,
  OFFH_GLU1    = OFFH_G3HH    + 256 * 768,
  OFFH_GLU2    = OFFH_GLU1    + 256 * 256,
  OFFH_GLU3    = OFFH_GLU2    + 256 * 256,
  OFFH_SKIP    = OFFH_GLU3    + 256 * 256,   // 8 x 1152 x 32
  OFFH_SKIPGLU = OFFH_SKIP    + 1152 * 256,
  WH_TOTAL     = OFFH_SKIPGLU + 256 * 256
};

enum : int {
  OFFC_C1  = 0,
  OFFC_C2  = OFFC_C1 + 336 * 336,
  OFFC_C3  = OFFC_C2 + 336 * 336,
  WC_TOTAL = OFFC_C3 + 336 * 512
};

__device__ __half g_wh[WH_TOTAL];
__device__ float  g_wc[WC_TOTAL];
__device__ float  g_cond[NFRAMES * NB * 512];

// dynamic smem layout (floats)
enum : int {
  DO_PARTA = 0,                            // 4*32*96 = 12288
  DO_PARTB = DO_PARTA + NROWS * 32 * 96,   // 12288
  DO_X     = DO_PARTB + NROWS * 32 * 96,   // 4*1152 = 4608
  DO_XG    = DO_X     + NROWS * 1152,      // 384
  DO_HG    = DO_XG    + NROWS * 96,        // 384
  DO_PREV  = DO_HG    + NROWS * 96,        // 1024
  DO_S1    = DO_PREV  + NROWS * 256,
  DO_S2    = DO_S1    + NROWS * 256,
  DO_S3    = DO_S2    + NROWS * 256,
  DO_S4    = DO_S3    + NROWS * 256,       // 1040
  DO_FW    = DO_S4    + NROWS * 260,
  DO_FW2   = DO_FW    + NROWS * 256,
  DO_O1    = DO_FW2   + NROWS * 256,
  DO_O2    = DO_O1    + NROWS * 256,
  DO_O3    = DO_O2    + NROWS * 256,
  DO_SK    = DO_O3    + NROWS * 256,
  DO_SK2   = DO_SK    + NROWS * 256,
  DO_PL    = DO_SK2   + NROWS * 256,       // 272
  DO_PSUB  = DO_PL    + NROWS * 68,        // 256
  DO_PG    = DO_PSUB  + NROWS * 64,        // 16
  DO_GAIN  = DO_PG    + NROWS * 4,         // 8
  DO_OUT   = DO_GAIN  + NROWS * 2,         // 256
  DO_TOTAL = DO_OUT   + NROWS * 64
};

// ---------------------------------------------------------------------------
__global__ void transpose_k(const float* __restrict__ src, float* __restrict__ dst,
                            int O, int I) {
  int idx = blockIdx.x * blockDim.x + threadIdx.x;
  if (idx < O * I) {
    int i = idx / O;
    int o = idx % O;
    dst[idx] = src[o * I + i];
  }
}

// 8-way reorg: src[O][I] -> dst[8][Ipad][O/8] fp16
__global__ void reorg_h8(const float* __restrict__ src, __half* __restrict__ dst,
                         int O, int I, int Ipad) {
  int idx = blockIdx.x * blockDim.x + threadIdx.x;
  if (idx >= O * Ipad) return;
  int i = idx / O, o = idx % O;
  int Oo = O >> 3;
  int r = o / Oo, c = o % Oo;
  float v = (i < I) ? src[o * I + i] : 0.f;
  dst[((size_t)r * Ipad + i) * Oo + c] = __float2half(v);
}

// 8-way GRU reorg (gate-permuted): w[768][I] -> dst[8][I][96]
__global__ void reorg_gru8(const float* __restrict__ src, __half* __restrict__ dst,
                           int I) {
  int idx = blockIdx.x * blockDim.x + threadIdx.x;
  if (idx >= 768 * I) return;
  int i = idx / 768, o = idx % 768;
  int s = o & 255, g = o >> 8;
  int r = s >> 5, c = g * 32 + (s & 31);
  dst[((size_t)r * I + i) * 96 + c] = __float2half(src[o * I + i]);
}

// ---------------------------------------------------------------------------
// 4-row fp16 GEMV partial, 1024 thr = 32 K-chunks x 32 lanes.
// lane: row = lane>>3, sub = lane&7.
template <int K, int NQ>
__device__ __forceinline__ void gemv4r(const __half* __restrict__ Wh,
                                       const float* __restrict__ xs, int rs,
                                       float* __restrict__ part) {
  const int tid  = threadIdx.x;
  const int kc   = tid >> 5;
  const int lane = tid & 31;
  const int row  = lane >> 3;
  const int sub  = lane & 7;
  constexpr int Kc = K / 32;
  const float* xk = xs + row * rs + kc * Kc;

  if (NQ == 32) {
    const float2* __restrict__ W2 =
        reinterpret_cast<const float2*>(Wh) + (size_t)(kc * Kc) * 8;
    float acc[4] = {0.f, 0.f, 0.f, 0.f};
#pragma unroll 4
    for (int k = 0; k < Kc; ++k) {
      const float xv = xk[k];
      float2 hw = W2[k * 8 + sub];
      const __half2* hp = reinterpret_cast<const __half2*>(&hw);
      float2 f0 = __half22float2(hp[0]);
      float2 f1 = __half22float2(hp[1]);
      acc[0] = fmaf(xv, f0.x, acc[0]);
      acc[1] = fmaf(xv, f0.y, acc[1]);
      acc[2] = fmaf(xv, f1.x, acc[2]);
      acc[3] = fmaf(xv, f1.y, acc[3]);
    }
    float4* P4 = reinterpret_cast<float4*>(part + (row * 32 + kc) * 32);
    P4[sub] = make_float4(acc[0], acc[1], acc[2], acc[3]);
  } else {  // NQ == 96
    const float2* __restrict__ W2 =
        reinterpret_cast<const float2*>(Wh) + (size_t)(kc * Kc) * 24;
    float acc[3][4];
#pragma unroll
    for (int j = 0; j < 3; ++j)
#pragma unroll
      for (int t = 0; t < 4; ++t) acc[j][t] = 0.f;
#pragma unroll 4
    for (int k = 0; k < Kc; ++k) {
      const float xv = xk[k];
#pragma unroll
      for (int j = 0; j < 3; ++j) {
        float2 hw = W2[k * 24 + sub + 8 * j];
        const __half2* hp = reinterpret_cast<const __half2*>(&hw);
        float2 f0 = __half22float2(hp[0]);
        float2 f1 = __half22float2(hp[1]);
        acc[j][0] = fmaf(xv, f0.x, acc[j][0]);
        acc[j][1] = fmaf(xv, f0.y, acc[j][1]);
        acc[j][2] = fmaf(xv, f1.x, acc[j][2]);
        acc[j][3] = fmaf(xv, f1.y, acc[j][3]);
      }
    }
    float4* P4 = reinterpret_cast<float4*>(part + (row * 32 + kc) * 96);
#pragma unroll
    for (int j = 0; j < 3; ++j)
      P4[sub + 8 * j] = make_float4(acc[j][0], acc[j][1], acc[j][2], acc[j][3]);
  }
}

__device__ __forceinline__ float csum4r(const float* __restrict__ part, int NQ,
                                        int row, int j) {
  const float* p = part + (row * 32) * NQ + j;
  float s = 0.f;
#pragma unroll
  for (int c = 0; c < 32; c += 4) {
    float a = p[c * NQ]       + p[(c + 1) * NQ];
    float b = p[(c + 2) * NQ] + p[(c + 3) * NQ];
    s += (a + b);
  }
  return s;
}

// ---------------------------------------------------------------------------
// conditioning net (unchanged)
__device__ __forceinline__ void gemv_part(const float* __restrict__ Wt,
                                          const float* __restrict__ xs,
                                          int K, int N, float* part) {
  const int tid = threadIdx.x;
  const int kc  = tid >> 6;
  const int g0  = tid & 63;
  const int Kc  = K >> 2;
  const int G   = N >> 2;
  const float4* __restrict__ W4 = reinterpret_cast<const float4*>(Wt) + (size_t)(kc * Kc) * G;
  const float*  __restrict__ xk = xs + kc * Kc;
  float4* P4 = reinterpret_cast<float4*>(part + kc * N);
  for (int g = g0; g < G; g += 64) {
    float4 acc = make_float4(0.f, 0.f, 0.f, 0.f);
    const float4* wp = W4 + g;
#pragma unroll 4
    for (int k = 0; k < Kc; ++k) {
      const float xv = xk[k];
      const float4 w = wp[(size_t)k * G];
      acc.x = fmaf(xv, w.x, acc.x);
      acc.y = fmaf(xv, w.y, acc.y);
      acc.z = fmaf(xv, w.z, acc.z);
      acc.w = fmaf(xv, w.w, acc.w);
    }
    P4[g] = acc;
  }
}
__device__ __forceinline__ float csum4(const float* part, int N, int j) {
  return (part[j] + part[N + j]) + (part[2 * N + j] + part[3 * N + j]);
}

__global__ __launch_bounds__(256)
void cond_kernel(const float* __restrict__ feat, const float* __restrict__ gf) {
  __shared__ __align__(16) float s_part[4 * 512];
  __shared__ float s_x[336];
  __shared__ float s_y[336];
  const int b = blockIdx.x, f = blockIdx.y, tid = threadIdx.x;

  for (int j = tid; j < 80; j += 256)  s_x[j]      = feat[(b * 80 + j) * NFRAMES + f];
  for (int j = tid; j < 256; j += 256) s_x[80 + j] = gf[b * 256 + j];
  __syncthreads();
  gemv_part(g_wc + OFFC_C1, s_x, 336, 336, s_part);
  __syncthreads();
  for (int j = tid; j < 336; j += 256) s_y[j] = tanhf(csum4(s_part, 336, j));
  __syncthreads();
  gemv_part(g_wc + OFFC_C2, s_y, 336, 336, s_part);
  __syncthreads();
  for (int j = tid; j < 336; j += 256) s_x[j] = tanhf(csum4(s_part, 336, j));
  __syncthreads();
  gemv_part(g_wc + OFFC_C3, s_x, 336, 512, s_part);
  __syncthreads();
  float* dst = g_cond + (f * NB + b) * 512;
  for (int j = tid; j < 512; j += 256) dst[j] = tanhf(csum4(s_part, 512, j));
}

// ---------------------------------------------------------------------------
// main kernel: 16 clusters of 8 CTAs; cluster q handles rows 4q..4q+3.
extern __shared__ float s_dyn[];

__global__ __launch_bounds__(NTHREADS, 1) __cluster_dims__(CLSZ, 1, 1)
void main_kernel(const float* __restrict__ prev0,
                 const int*   __restrict__ periods,
                 const float* __restrict__ gain_w,
                 const float* __restrict__ gain_b,
                 const float* __restrict__ pg_w,
                 const float* __restrict__ pg_b,
                 const float* __restrict__ out_w,
                 float*       __restrict__ outp) {
  float* PART_A = s_dyn + DO_PARTA;
  float* PART_B = s_dyn + DO_PARTB;
  float* s_x    = s_dyn + DO_X;
  float* s_xg   = s_dyn + DO_XG;
  float* s_hg   = s_dyn + DO_HG;
  float* s_prev = s_dyn + DO_PREV;
  float* s_s1   = s_dyn + DO_S1;
  float* s_s2   = s_dyn + DO_S2;
  float* s_s3   = s_dyn + DO_S3;
  float* s_s4   = s_dyn + DO_S4;
  float* s_fw   = s_dyn + DO_FW;
  float* s_fw2  = s_dyn + DO_FW2;
  float* s_o1   = s_dyn + DO_O1;
  float* s_o2   = s_dyn + DO_O2;
  float* s_o3   = s_dyn + DO_O3;
  float* s_sk   = s_dyn + DO_SK;
  float* s_sk2  = s_dyn + DO_SK2;
  float* s_pl   = s_dyn + DO_PL;
  float* s_psub = s_dyn + DO_PSUB;
  float* s_pg   = s_dyn + DO_PG;
  float* s_gain = s_dyn + DO_GAIN;
  float* s_out  = s_dyn + DO_OUT;

  const int tid  = threadIdx.x;
  const int rank = blockIdx.x & (CLSZ - 1);
  const int q    = blockIdx.x / CLSZ;

  auto exch = [&](float* addr, float v) {
    *addr = v;
    uint32_t a = s2u_(addr);
#pragma unroll
    for (int p = 1; p < CLSZ; ++p) st_peer_(mapa_u_(a, (rank + p) & (CLSZ - 1)), v);
  };

  if (tid < NROWS * 256) {
    s_prev[tid] = prev0[q * (NROWS * 256) + tid];
    s_s1[tid] = 0.f; s_s2[tid] = 0.f; s_s3[tid] = 0.f;
  }
  for (int idx = tid; idx < NROWS * 260; idx += NTHREADS) s_s4[idx] = 0.f;
  __syncthreads();

  const float gb0 = gain_b[0];
  int per[NROWS];
  const float* condr[NROWS];

  for (int f = 0; f < NFRAMES; ++f) {
#pragma unroll
    for (int r = 0; r < NROWS; ++r) {
      per[r] = periods[(q * NROWS + r) * NFRAMES + f];
      condr[r] = g_cond + (f * NB + q * NROWS + r) * 512;
    }

    for (int i = 0; i < 4; ++i) {
      // ---- gain: warp r computes row r (redundant across CTAs)
      if (tid < NROWS * 32) {
        int row = tid >> 5, l = tid & 31;
        const float* sf = condr[row] + i * 128;
        float d = 0.f;
        for (int k = l; k < 128; k += 32) d = fmaf(sf[k], gain_w[k], d);
#pragma unroll
        for (int o = 16; o; o >>= 1) d += __shfl_xor_sync(0xffffffffu, d, o);
        if (l == 0) {
          float g = expf(d + gb0);
          s_gain[row * 2]     = g;
          s_gain[row * 2 + 1] = 1.0f / (1e-5f + g);
        }
      }
      __syncthreads();

      // ---- pitch gather + psub per row
      if (tid < NROWS * 68) {
        int row = tid / 68, t = tid % 68;
        int idx = 256 - per[row] + t - 2;
        if (idx >= 256) idx -= per[row];
        s_pl[row * 68 + t] = s_prev[row * 256 + idx] * s_gain[row * 2 + 1];
      } else if (tid >= 512 && tid < 512 + NROWS * 64) {
        int row = (tid - 512) >> 6, t = (tid - 512) & 63;
        s_psub[row * 64 + t] = s_prev[row * 256 + 192 + t] * s_gain[row * 2 + 1];
      }
      __syncthreads();

      // ---- fw input: per row [sf(128), psub(64), pl(68), s4(260), pad] = 544
      for (int idx = tid; idx < NROWS * 544; idx += NTHREADS) {
        int row = idx / 544, p = idx % 544;
        float v;
        if (p < 128)       v = condr[row][i * 128 + p];
        else if (p < 192)  v = s_psub[row * 64 + (p - 128)];
        else if (p < 260)  v = s_pl[row * 68 + (p - 192)];
        else if (p < 520)  v = s_s4[row * 260 + (p - 260)];
        else               v = 0.f;
        s_x[row * 1152 + p] = v;
      }
      __syncthreads();
      // s4 <- sif (x[0:260]); stable during gemv
      for (int idx = tid; idx < NROWS * 260; idx += NTHREADS) {
        int row = idx / 260, t = idx % 260;
        s_s4[row * 260 + t] = s_x[row * 1152 + t];
      }

      gemv4r<544, 32>(g_wh + OFFH_FW + rank * 544 * 32, s_x, 1152, PART_A);
      __syncthreads();
      if (tid < NROWS * 32) {
        int row = tid >> 5, jl = tid & 31;
        exch(&s_fw[row * 256 + rank * 32 + jl], tanhf(csum4r(PART_A, 32, row, jl)));
      }
      CLUSTER_SYNC_();

      gemv4r<256, 32>(g_wh + OFFH_FWGLU + rank * 256 * 32, s_fw, 256, PART_A);
      __syncthreads();
      if (tid < NROWS * 32) {
        int row = tid >> 5, jl = tid & 31;
        int j = rank * 32 + jl;
        float v = s_fw[row * 256 + j] * sigmoidf_(csum4r(PART_A, 32, row, jl));
        exch(&s_fw2[row * 256 + j], v);
      }
      CLUSTER_SYNC_();

      // ---- pg: 16 warps (row, gate) redundant per CTA
      if (tid < NROWS * 128) {
        int w = tid >> 5, l = tid & 31;
        int row = w >> 2, g = w & 3;
        float d = 0.f;
        for (int k = l; k < 256; k += 32)
          d = fmaf(s_fw2[row * 256 + k], pg_w[g * 256 + k], d);
#pragma unroll
        for (int o = 16; o; o >>= 1) d += __shfl_xor_sync(0xffffffffu, d, o);
        if (l == 0) s_pg[row * 4 + g] = sigmoidf_(d + pg_b[g]) + 1e-5f;
      }
      __syncthreads();

      // ================= GRU + GLU macros =================
#define GRU_STAGE(SRC, OFF_IH, OFF_HH, SSTATE, PGI)                              \
      for (int idx = tid; idx < NROWS * 384; idx += NTHREADS) {                  \
        int row = idx / 384, p = idx % 384;                                      \
        float v;                                                                 \
        if (p < 256)       v = SRC[row * 256 + p];                               \
        else if (p < 320)  v = s_pg[row * 4 + PGI] * s_pl[row * 68 + 2 + (p - 256)]; \
        else               v = s_psub[row * 64 + (p - 320)];                     \
        s_x[row * 1152 + p] = v;                                                 \
      }                                                                          \
      __syncthreads();                                                           \
      gemv4r<384, 96>(g_wh + OFF_IH + rank * 384 * 96, s_x, 1152, PART_A);       \
      gemv4r<256, 96>(g_wh + OFF_HH + rank * 256 * 96, SSTATE, 256, PART_B);     \
      __syncthreads();                                                           \
      if (tid < 2 * NROWS * 96) {                                                \
        int arr = tid / (NROWS * 96), t = tid % (NROWS * 96);                    \
        int row = t / 96, c = t % 96;                                            \
        if (arr == 0) s_xg[row * 96 + c] = csum4r(PART_A, 96, row, c);           \
        else          s_hg[row * 96 + c] = csum4r(PART_B, 96, row, c);           \
      }                                                                          \
      __syncthreads();                                                           \
      if (tid < NROWS * 32) {                                                    \
        int row = tid >> 5, sl = tid & 31;                                       \
        float r = sigmoidf_(s_xg[row * 96 + sl]      + s_hg[row * 96 + sl]);     \
        float z = sigmoidf_(s_xg[row * 96 + 32 + sl] + s_hg[row * 96 + 32 + sl]); \
        float n = tanhf(s_xg[row * 96 + 64 + sl] + r * s_hg[row * 96 + 64 + sl]); \
        int j = rank * 32 + sl;                                                  \
        float v = (1.f - z) * n + z * SSTATE[row * 256 + j];                     \
        exch(&SSTATE[row * 256 + j], v);                                         \
      }                                                                          \
      CLUSTER_SYNC_();

#define GLU_STAGE(OFF_GLU, SSTATE, DST)                                          \
      gemv4r<256, 32>(g_wh + OFF_GLU + rank * 256 * 32, SSTATE, 256, PART_A);    \
      __syncthreads();                                                           \
      if (tid < NROWS * 32) {                                                    \
        int row = tid >> 5, jl = tid & 31;                                       \
        int j = rank * 32 + jl;                                                  \
        float v = SSTATE[row * 256 + j] * sigmoidf_(csum4r(PART_A, 32, row, jl)); \
        exch(&DST[row * 256 + j], v);                                            \
      }                                                                          \
      CLUSTER_SYNC_();

      GRU_STAGE(s_fw2, OFFH_G1IH, OFFH_G1HH, s_s1, 0)
      GLU_STAGE(OFFH_GLU1, s_s1, s_o1)
      GRU_STAGE(s_o1, OFFH_G2IH, OFFH_G2HH, s_s2, 1)
      GLU_STAGE(OFFH_GLU2, s_s2, s_o2)
      GRU_STAGE(s_o2, OFFH_G3IH, OFFH_G3HH, s_s3, 2)
      GLU_STAGE(OFFH_GLU3, s_s3, s_o3)
#undef GRU_STAGE
#undef GLU_STAGE

      // ---- skip input: per row [o1,o2,o3,fw2,pg3*pl2,psub] = 1152
      for (int idx = tid; idx < NROWS * 1152; idx += NTHREADS) {
        int row = idx / 1152, p = idx % 1152;
        float v;
        if (p < 256)        v = s_o1[row * 256 + p];
        else if (p < 512)   v = s_o2[row * 256 + (p - 256)];
        else if (p < 768)   v = s_o3[row * 256 + (p - 512)];
        else if (p < 1024)  v = s_fw2[row * 256 + (p - 768)];
        else if (p < 1088)  v = s_pg[row * 4 + 3] * s_pl[row * 68 + 2 + (p - 1024)];
        else                v = s_psub[row * 64 + (p - 1088)];
        s_x[row * 1152 + p] = v;
      }
      __syncthreads();
      gemv4r<1152, 32>(g_wh + OFFH_SKIP + rank * 1152 * 32, s_x, 1152, PART_A);
      __syncthreads();
      if (tid < NROWS * 32) {
        int row = tid >> 5, jl = tid & 31;
        exch(&s_sk[row * 256 + rank * 32 + jl], tanhf(csum4r(PART_A, 32, row, jl)));
      }
      CLUSTER_SYNC_();

      gemv4r<256, 32>(g_wh + OFFH_SKIPGLU + rank * 256 * 32, s_sk, 256, PART_A);
      __syncthreads();
      if (tid < NROWS * 32) {
        int row = tid >> 5, jl = tid & 31;
        int j = rank * 32 + jl;
        float v = s_sk[row * 256 + j] * sigmoidf_(csum4r(PART_A, 32, row, jl));
        exch(&s_sk2[row * 256 + j], v);
      }
      CLUSTER_SYNC_();

      // ---- out: warp w -> row = w>>3, o = rank*8 + (w&7)
      {
        const int w = tid >> 5, l = tid & 31;
        const int row = w >> 3, o = rank * 8 + (w & 7);
        const float4* wr = reinterpret_cast<const float4*>(out_w + o * 256) + l * 2;
        const float4* xr = reinterpret_cast<const float4*>(s_sk2 + row * 256) + l * 2;
        float4 wa = wr[0], wb = wr[1];
        float4 xa = xr[0], xb = xr[1];
        float d = wa.x * xa.x + wa.y * xa.y + wa.z * xa.z + wa.w * xa.w
                + wb.x * xb.x + wb.y * xb.y + wb.z * xb.z + wb.w * xb.w;
#pragma unroll
        for (int oo = 16; oo; oo >>= 1) d += __shfl_xor_sync(0xffffffffu, d, oo);
        if (l == 0) {
          float v = tanhf(d) * s_gain[row * 2];
          exch(&s_out[row * 64 + o], v);
          outp[(q * NROWS + row) * 25600 + f * 256 + i * 64 + o] = v;
        }
      }
      CLUSTER_SYNC_();

      // ---- prev = [prev[64:], out] per row
      float pv = 0.f;
      {
        int row = tid >> 8, t = tid & 255;
        pv = (t < 192) ? s_prev[row * 256 + t + 64] : s_out[row * 64 + (t - 192)];
      }
      __syncthreads();
      s_prev[tid] = pv;
      __syncthreads();
    }
  }
}

// ---------------------------------------------------------------------------
extern "C" void kernel_launch(void* const* d_in, const int* in_sizes, int n_in,
                              void* d_out, int out_size) {
  (void)in_sizes; (void)n_in; (void)out_size;
  const float* features = (const float*)d_in[0];
  const float* gfeat    = (const float*)d_in[1];
  const float* prev     = (const float*)d_in[2];
  const int*   periods  = (const int*)d_in[3];
  const float* cond_w1  = (const float*)d_in[4];
  const float* cond_w2  = (const float*)d_in[5];
  const float* cond_w3  = (const float*)d_in[6];
  const float* gain_w   = (const float*)d_in[7];
  const float* gain_b   = (const float*)d_in[8];
  const float* fw_w     = (const float*)d_in[9];
  const float* fw_glu_w = (const float*)d_in[10];
  const float* pg_w     = (const float*)d_in[11];
  const float* pg_b     = (const float*)d_in[12];
  const float* g1ih     = (const float*)d_in[13];
  const float* g1hh     = (const float*)d_in[14];
  const float* g2ih     = (const float*)d_in[15];
  const float* g2hh     = (const float*)d_in[16];
  const float* g3ih     = (const float*)d_in[17];
  const float* g3hh     = (const float*)d_in[18];
  const float* glu1     = (const float*)d_in[19];
  const float* glu2     = (const float*)d_in[20];
  const float* glu3     = (const float*)d_in[21];
  const float* skip_w   = (const float*)d_in[22];
  const float* skipglu  = (const float*)d_in[23];
  const float* out_w    = (const float*)d_in[24];

  __half* wh = nullptr;
  float*  wc = nullptr;
  cudaGetSymbolAddress((void**)&wh, g_wh);
  cudaGetSymbolAddress((void**)&wc, g_wc);

  auto rg8 = [&](const float* src, int off, int O, int I, int Ipad) {
    int tot = O * Ipad;
    reorg_h8<<<(tot + 255) / 256, 256>>>(src, wh + off, O, I, Ipad);
  };
  auto rgg = [&](const float* src, int off, int I) {
    int tot = 768 * I;
    reorg_gru8<<<(tot + 255) / 256, 256>>>(src, wh + off, I);
  };
  auto tpc = [&](const float* src, int off, int O, int I) {
    int tot = O * I;
    transpose_k<<<(tot + 255) / 256, 256>>>(src, wc + off, O, I);
  };

  rg8(fw_w,     OFFH_FW,      256, 520, 544);
  rg8(fw_glu_w, OFFH_FWGLU,   256, 256, 256);
  rgg(g1ih,     OFFH_G1IH,    384);
  rgg(g1hh,     OFFH_G1HH,    256);
  rgg(g2ih,     OFFH_G2IH,    384);
  rgg(g2hh,     OFFH_G2HH,    256);
  rgg(g3ih,     OFFH_G3IH,    384);
  rgg(g3hh,     OFFH_G3HH,    256);
  rg8(glu1,     OFFH_GLU1,    256, 256, 256);
  rg8(glu2,     OFFH_GLU2,    256, 256, 256);
  rg8(glu3,     OFFH_GLU3,    256, 256, 256);
  rg8(skip_w,   OFFH_SKIP,    256, 1152, 1152);
  rg8(skipglu,  OFFH_SKIPGLU, 256, 256, 256);
  tpc(cond_w1,  OFFC_C1,      336, 336);
  tpc(cond_w2,  OFFC_C2,      336, 336);
  tpc(cond_w3,  OFFC_C3,      512, 336);

  dim3 cg(NB, NFRAMES);
  cond_kernel<<<cg, 256>>>(features, gfeat);

  const int dyn_smem = DO_TOTAL * (int)sizeof(float);  // ~168 KB
  cudaFuncSetAttribute(main_kernel, cudaFuncAttributeMaxDynamicSharedMemorySize, dyn_smem);
  main_kernel<<<16 * CLSZ, NTHREADS, dyn_smem>>>(prev, periods, gain_w, gain_b,
                                                 pg_w, pg_b, out_w, (float*)d_out);
}

// round 12
// speedup vs baseline: 1.4347x; 1.4347x over previous
#include <cuda_runtime.h>
#include <cuda_fp16.h>
#include <stdint.h>
#include <math.h>

// ----------------------------------------------------------------------------
// FARGAN vocoder. Round 11: CLSZ=4 clusters (proven schedulable), NROWS=4
// batch rows per cluster -> 16 clusters x 4 = 64 CTAs, single wave.
// Chip weight traffic 72 MB/subframe. Each loaded weight is applied to all
// 4 rows in registers (no load duplication). GRU IH/HH computed concurrently
// on warp halves. fp16 K-major weights, fp32 accumulate, 1024 threads/CTA.
// ----------------------------------------------------------------------------

#define NFRAMES 100
#define NB      64
#define NTHREADS 1024
#define NROWS   4
#define CLSZ    4

__device__ __forceinline__ float sigmoidf_(float x) { return 1.0f / (1.0f + expf(-x)); }

__device__ __forceinline__ uint32_t s2u_(const void* p) {
  uint32_t a;
  asm("{ .reg .u64 t; cvta.to.shared.u64 t, %1; cvt.u32.u64 %0, t; }" : "=r"(a) : "l"(p));
  return a;
}
__device__ __forceinline__ uint32_t mapa_u_(uint32_t a, uint32_t r) {
  uint32_t d;
  asm("mapa.shared::cluster.u32 %0, %1, %2;" : "=r"(d) : "r"(a), "r"(r));
  return d;
}
__device__ __forceinline__ void st_peer_(uint32_t a, float v) {
  asm volatile("st.shared::cluster.f32 [%0], %1;" :: "r"(a), "f"(v));
}
#define CLUSTER_SYNC_() do { \
  asm volatile("barrier.cluster.arrive.aligned;" ::: "memory"); \
  asm volatile("barrier.cluster.wait.aligned;" ::: "memory"); \
} while (0)

// fp16 weights, 4 rank-slices per matrix: small [4][Kpad][64], GRU [4][K][192]
enum : int {
  OFFH_FW      = 0,                          // 4 x 576 x 64 (520 padded)
  OFFH_FWGLU   = OFFH_FW      + 576 * 256,
  OFFH_G1IH    = OFFH_FWGLU   + 256 * 256,   // 4 x 384 x 192
  OFFH_G1HH    = OFFH_G1IH    + 384 * 768,   // 4 x 256 x 192
  OFFH_G2IH    = OFFH_G1HH    + 256 * 768,
  OFFH_G2HH    = OFFH_G2IH    + 384 * 768,
  OFFH_G3IH    = OFFH_G2HH    + 256 * 768,
  OFFH_G3HH    = OFFH_G3IH    + 384 * 768,
  OFFH_GLU1    = OFFH_G3HH    + 256 * 768,
  OFFH_GLU2    = OFFH_GLU1    + 256 * 256,
  OFFH_GLU3    = OFFH_GLU2    + 256 * 256,
  OFFH_SKIP    = OFFH_GLU3    + 256 * 256,   // 4 x 1152 x 64
  OFFH_SKIPGLU = OFFH_SKIP    + 1152 * 256,
  WH_TOTAL     = OFFH_SKIPGLU + 256 * 256
};

enum : int {
  OFFC_C1  = 0,
  OFFC_C2  = OFFC_C1 + 336 * 336,
  OFFC_C3  = OFFC_C2 + 336 * 336,
  WC_TOTAL = OFFC_C3 + 336 * 512
};

__device__ __half g_wh[WH_TOTAL];
__device__ float  g_wc[WC_TOTAL];
__device__ float  g_cond[NFRAMES * NB * 512];

// dynamic smem layout (floats)
enum : int {
  DO_PARTA = 0,                            // max(4*16*192, 4*32*64) = 12288
  DO_PARTB = DO_PARTA + 12288,             // 12288
  DO_X     = DO_PARTB + 12288,             // 4*1152
  DO_XG    = DO_X     + NROWS * 1152,      // 768
  DO_HG    = DO_XG    + NROWS * 192,
  DO_PREV  = DO_HG    + NROWS * 192,
  DO_S1    = DO_PREV  + NROWS * 256,
  DO_S2    = DO_S1    + NROWS * 256,
  DO_S3    = DO_S2    + NROWS * 256,
  DO_S4    = DO_S3    + NROWS * 256,
  DO_FW    = DO_S4    + NROWS * 260,
  DO_FW2   = DO_FW    + NROWS * 256,
  DO_O1    = DO_FW2   + NROWS * 256,
  DO_O2    = DO_O1    + NROWS * 256,
  DO_O3    = DO_O2    + NROWS * 256,
  DO_SK    = DO_O3    + NROWS * 256,
  DO_SK2   = DO_SK    + NROWS * 256,
  DO_PL    = DO_SK2   + NROWS * 256,
  DO_PSUB  = DO_PL    + NROWS * 68,
  DO_PG    = DO_PSUB  + NROWS * 64,
  DO_GAIN  = DO_PG    + NROWS * 4,
  DO_OUT   = DO_GAIN  + NROWS * 2,
  DO_TOTAL = DO_OUT   + NROWS * 64
};

// ---------------------------------------------------------------------------
__global__ void transpose_k(const float* __restrict__ src, float* __restrict__ dst,
                            int O, int I) {
  int idx = blockIdx.x * blockDim.x + threadIdx.x;
  if (idx < O * I) {
    int i = idx / O;
    int o = idx % O;
    dst[idx] = src[o * I + i];
  }
}

// 4-way reorg: src[O][I] -> dst[4][Ipad][O/4] fp16
__global__ void reorg_h4(const float* __restrict__ src, __half* __restrict__ dst,
                         int O, int I, int Ipad) {
  int idx = blockIdx.x * blockDim.x + threadIdx.x;
  if (idx >= O * Ipad) return;
  int i = idx / O, o = idx % O;
  int Oq = O >> 2;
  int r = o / Oq, c = o % Oq;
  float v = (i < I) ? src[o * I + i] : 0.f;
  dst[((size_t)r * Ipad + i) * Oq + c] = __float2half(v);
}

// 4-way GRU reorg (gate-permuted): w[768][I] -> dst[4][I][192]
// s=o%256, g=o/256; rank=s/64; col=g*64+(s%64)
__global__ void reorg_gru4(const float* __restrict__ src, __half* __restrict__ dst,
                           int I) {
  int idx = blockIdx.x * blockDim.x + threadIdx.x;
  if (idx >= 768 * I) return;
  int i = idx / 768, o = idx % 768;
  int s = o & 255, g = o >> 8;
  int r = s >> 6, c = g * 64 + (s & 63);
  dst[((size_t)r * I + i) * 192 + c] = __float2half(src[o * I + i]);
}

// ---------------------------------------------------------------------------
// Small-stage GEMV: outputs 64 cols x 4 rows. 64 K-chunks = 32 warps x 2 kk.
// Each thread: float2 weight load (4 cols), applied to 4 rows (16 fp32 accums).
// In-warp shfl reduce over kk; lanes kk==0 write part[(row*32+w)*64 + col].
template <int K>
__device__ __forceinline__ void gemv_small(const __half* __restrict__ Wh,
                                           const float* __restrict__ xs, int rs,
                                           float* __restrict__ part) {
  const int tid = threadIdx.x;
  const int w = tid >> 5, lane = tid & 31;
  const int kk = lane >> 4, sub = lane & 15;
  constexpr int Kc = K / 64;
  const int kbase = (w * 2 + kk) * Kc;
  const float2* __restrict__ W2 =
      reinterpret_cast<const float2*>(Wh) + (size_t)kbase * 16 + sub;

  float acc[4][4];
#pragma unroll
  for (int r = 0; r < 4; ++r)
#pragma unroll
    for (int c = 0; c < 4; ++c) acc[r][c] = 0.f;

#pragma unroll
  for (int t = 0; t < Kc; ++t) {
    const int k = kbase + t;
    float2 hw = W2[t * 16];
    const __half2* hp = reinterpret_cast<const __half2*>(&hw);
    float2 f0 = __half22float2(hp[0]);
    float2 f1 = __half22float2(hp[1]);
#pragma unroll
    for (int r = 0; r < 4; ++r) {
      const float xv = xs[r * rs + k];
      acc[r][0] = fmaf(xv, f0.x, acc[r][0]);
      acc[r][1] = fmaf(xv, f0.y, acc[r][1]);
      acc[r][2] = fmaf(xv, f1.x, acc[r][2]);
      acc[r][3] = fmaf(xv, f1.y, acc[r][3]);
    }
  }
#pragma unroll
  for (int r = 0; r < 4; ++r)
#pragma unroll
    for (int c = 0; c < 4; ++c)
      acc[r][c] += __shfl_xor_sync(0xffffffffu, acc[r][c], 16);
  if (kk == 0) {
#pragma unroll
    for (int r = 0; r < 4; ++r)
      reinterpret_cast<float4*>(part + (r * 32 + w) * 64)[sub] =
          make_float4(acc[r][0], acc[r][1], acc[r][2], acc[r][3]);
  }
}

__device__ __forceinline__ float csum_small(const float* __restrict__ p,
                                            int row, int col) {
  const float* q = p + row * 32 * 64 + col;
  float s = 0.f;
#pragma unroll
  for (int c = 0; c < 32; c += 4) {
    float a = q[c * 64]       + q[(c + 1) * 64];
    float b = q[(c + 2) * 64] + q[(c + 3) * 64];
    s += (a + b);
  }
  return s;
}

// ---------------------------------------------------------------------------
// GRU dual GEMV: warps 0..15 do IH (K=384), warps 16..31 do HH (K=256),
// both into 192 cols x 4 rows. 16 chunks each; lane 0..23 owns one float4
// col-group (8 cols), applied to 4 rows (32 fp32 accums).
__device__ __forceinline__ void gemv_gru(const __half* __restrict__ Wih,
                                         const __half* __restrict__ Whh,
                                         const float* __restrict__ x, int rsx,
                                         const float* __restrict__ h,
                                         float* __restrict__ pA,
                                         float* __restrict__ pB) {
  const int tid = threadIdx.x;
  const int w = tid >> 5, lane = tid & 31;
  if (lane >= 24) return;
  const bool ih = (w < 16);
  const __half* Wh = ih ? Wih : Whh;
  const float* xs  = ih ? x : h;
  const int rs     = ih ? rsx : 256;
  const int Kc     = ih ? 24 : 16;
  float* part      = ih ? pA : pB;
  const int c = w & 15;
  const int kbase = c * Kc;
  const float4* __restrict__ W4 =
      reinterpret_cast<const float4*>(Wh) + (size_t)kbase * 24 + lane;

  float acc[4][8];
#pragma unroll
  for (int r = 0; r < 4; ++r)
#pragma unroll
    for (int j = 0; j < 8; ++j) acc[r][j] = 0.f;

#pragma unroll 4
  for (int t = 0; t < Kc; ++t) {
    const int k = kbase + t;
    float4 hw = W4[(size_t)t * 24];
    const __half2* hp = reinterpret_cast<const __half2*>(&hw);
    float2 f0 = __half22float2(hp[0]);
    float2 f1 = __half22float2(hp[1]);
    float2 f2 = __half22float2(hp[2]);
    float2 f3 = __half22float2(hp[3]);
#pragma unroll
    for (int r = 0; r < 4; ++r) {
      const float xv = xs[r * rs + k];
      acc[r][0] = fmaf(xv, f0.x, acc[r][0]);
      acc[r][1] = fmaf(xv, f0.y, acc[r][1]);
      acc[r][2] = fmaf(xv, f1.x, acc[r][2]);
      acc[r][3] = fmaf(xv, f1.y, acc[r][3]);
      acc[r][4] = fmaf(xv, f2.x, acc[r][4]);
      acc[r][5] = fmaf(xv, f2.y, acc[r][5]);
      acc[r][6] = fmaf(xv, f3.x, acc[r][6]);
      acc[r][7] = fmaf(xv, f3.y, acc[r][7]);
    }
  }
#pragma unroll
  for (int r = 0; r < 4; ++r) {
    float4* P = reinterpret_cast<float4*>(part + (r * 16 + c) * 192 + lane * 8);
    P[0] = make_float4(acc[r][0], acc[r][1], acc[r][2], acc[r][3]);
    P[1] = make_float4(acc[r][4], acc[r][5], acc[r][6], acc[r][7]);
  }
}

__device__ __forceinline__ float csum_gru(const float* __restrict__ p,
                                          int row, int col) {
  const float* q = p + row * 16 * 192 + col;
  float s = 0.f;
#pragma unroll
  for (int c = 0; c < 16; c += 4) {
    float a = q[c * 192]       + q[(c + 1) * 192];
    float b = q[(c + 2) * 192] + q[(c + 3) * 192];
    s += (a + b);
  }
  return s;
}

// ---------------------------------------------------------------------------
// conditioning net (unchanged)
__device__ __forceinline__ void gemv_part(const float* __restrict__ Wt,
                                          const float* __restrict__ xs,
                                          int K, int N, float* part) {
  const int tid = threadIdx.x;
  const int kc  = tid >> 6;
  const int g0  = tid & 63;
  const int Kc  = K >> 2;
  const int G   = N >> 2;
  const float4* __restrict__ W4 = reinterpret_cast<const float4*>(Wt) + (size_t)(kc * Kc) * G;
  const float*  __restrict__ xk = xs + kc * Kc;
  float4* P4 = reinterpret_cast<float4*>(part + kc * N);
  for (int g = g0; g < G; g += 64) {
    float4 acc = make_float4(0.f, 0.f, 0.f, 0.f);
    const float4* wp = W4 + g;
#pragma unroll 4
    for (int k = 0; k < Kc; ++k) {
      const float xv = xk[k];
      const float4 w = wp[(size_t)k * G];
      acc.x = fmaf(xv, w.x, acc.x);
      acc.y = fmaf(xv, w.y, acc.y);
      acc.z = fmaf(xv, w.z, acc.z);
      acc.w = fmaf(xv, w.w, acc.w);
    }
    P4[g] = acc;
  }
}
__device__ __forceinline__ float csum4(const float* part, int N, int j) {
  return (part[j] + part[N + j]) + (part[2 * N + j] + part[3 * N + j]);
}

__global__ __launch_bounds__(256)
void cond_kernel(const float* __restrict__ feat, const float* __restrict__ gf) {
  __shared__ __align__(16) float s_part[4 * 512];
  __shared__ float s_x[336];
  __shared__ float s_y[336];
  const int b = blockIdx.x, f = blockIdx.y, tid = threadIdx.x;

  for (int j = tid; j < 80; j += 256)  s_x[j]      = feat[(b * 80 + j) * NFRAMES + f];
  for (int j = tid; j < 256; j += 256) s_x[80 + j] = gf[b * 256 + j];
  __syncthreads();
  gemv_part(g_wc + OFFC_C1, s_x, 336, 336, s_part);
  __syncthreads();
  for (int j = tid; j < 336; j += 256) s_y[j] = tanhf(csum4(s_part, 336, j));
  __syncthreads();
  gemv_part(g_wc + OFFC_C2, s_y, 336, 336, s_part);
  __syncthreads();
  for (int j = tid; j < 336; j += 256) s_x[j] = tanhf(csum4(s_part, 336, j));
  __syncthreads();
  gemv_part(g_wc + OFFC_C3, s_x, 336, 512, s_part);
  __syncthreads();
  float* dst = g_cond + (f * NB + b) * 512;
  for (int j = tid; j < 512; j += 256) dst[j] = tanhf(csum4(s_part, 512, j));
}

// ---------------------------------------------------------------------------
// main kernel: 16 clusters of 4 CTAs; cluster q handles rows 4q..4q+3.
extern __shared__ float s_dyn[];

__global__ __launch_bounds__(NTHREADS, 1) __cluster_dims__(CLSZ, 1, 1)
void main_kernel(const float* __restrict__ prev0,
                 const int*   __restrict__ periods,
                 const float* __restrict__ gain_w,
                 const float* __restrict__ gain_b,
                 const float* __restrict__ pg_w,
                 const float* __restrict__ pg_b,
                 const float* __restrict__ out_w,
                 float*       __restrict__ outp) {
  float* PART_A = s_dyn + DO_PARTA;
  float* PART_B = s_dyn + DO_PARTB;
  float* s_x    = s_dyn + DO_X;
  float* s_xg   = s_dyn + DO_XG;
  float* s_hg   = s_dyn + DO_HG;
  float* s_prev = s_dyn + DO_PREV;
  float* s_s1   = s_dyn + DO_S1;
  float* s_s2   = s_dyn + DO_S2;
  float* s_s3   = s_dyn + DO_S3;
  float* s_s4   = s_dyn + DO_S4;
  float* s_fw   = s_dyn + DO_FW;
  float* s_fw2  = s_dyn + DO_FW2;
  float* s_o1   = s_dyn + DO_O1;
  float* s_o2   = s_dyn + DO_O2;
  float* s_o3   = s_dyn + DO_O3;
  float* s_sk   = s_dyn + DO_SK;
  float* s_sk2  = s_dyn + DO_SK2;
  float* s_pl   = s_dyn + DO_PL;
  float* s_psub = s_dyn + DO_PSUB;
  float* s_pg   = s_dyn + DO_PG;
  float* s_gain = s_dyn + DO_GAIN;
  float* s_out  = s_dyn + DO_OUT;

  const int tid  = threadIdx.x;
  const int rank = blockIdx.x & (CLSZ - 1);
  const int q    = blockIdx.x / CLSZ;

  auto exch = [&](float* addr, float v) {
    *addr = v;
    uint32_t a = s2u_(addr);
#pragma unroll
    for (int p = 1; p < CLSZ; ++p) st_peer_(mapa_u_(a, (rank + p) & (CLSZ - 1)), v);
  };

  {
    s_prev[tid] = prev0[q * (NROWS * 256) + tid];
    s_s1[tid] = 0.f; s_s2[tid] = 0.f; s_s3[tid] = 0.f;
  }
  for (int idx = tid; idx < NROWS * 260; idx += NTHREADS) s_s4[idx] = 0.f;
  __syncthreads();

  const float gb0 = gain_b[0];
  int per[NROWS];
  const float* condr[NROWS];

  for (int f = 0; f < NFRAMES; ++f) {
#pragma unroll
    for (int r = 0; r < NROWS; ++r) {
      per[r] = periods[(q * NROWS + r) * NFRAMES + f];
      condr[r] = g_cond + (f * NB + q * NROWS + r) * 512;
    }

    for (int i = 0; i < 4; ++i) {
      // ---- gain: warp r computes row r
      if (tid < NROWS * 32) {
        int row = tid >> 5, l = tid & 31;
        const float* sf = condr[row] + i * 128;
        float d = 0.f;
        for (int k = l; k < 128; k += 32) d = fmaf(sf[k], gain_w[k], d);
#pragma unroll
        for (int o = 16; o; o >>= 1) d += __shfl_xor_sync(0xffffffffu, d, o);
        if (l == 0) {
          float g = expf(d + gb0);
          s_gain[row * 2]     = g;
          s_gain[row * 2 + 1] = 1.0f / (1e-5f + g);
        }
      }
      __syncthreads();

      // ---- pitch gather + psub per row
      if (tid < NROWS * 68) {
        int row = tid / 68, t = tid % 68;
        int idx = 256 - per[row] + t - 2;
        if (idx >= 256) idx -= per[row];
        s_pl[row * 68 + t] = s_prev[row * 256 + idx] * s_gain[row * 2 + 1];
      } else if (tid >= 512 && tid < 512 + NROWS * 64) {
        int row = (tid - 512) >> 6, t = (tid - 512) & 63;
        s_psub[row * 64 + t] = s_prev[row * 256 + 192 + t] * s_gain[row * 2 + 1];
      }
      __syncthreads();

      // ---- fw input: per row [sf(128), psub(64), pl(68), s4(260), pad] = 576
      for (int idx = tid; idx < NROWS * 576; idx += NTHREADS) {
        int row = idx / 576, p = idx % 576;
        float v;
        if (p < 128)       v = condr[row][i * 128 + p];
        else if (p < 192)  v = s_psub[row * 64 + (p - 128)];
        else if (p < 260)  v = s_pl[row * 68 + (p - 192)];
        else if (p < 520)  v = s_s4[row * 260 + (p - 260)];
        else               v = 0.f;
        s_x[row * 1152 + p] = v;
      }
      __syncthreads();
      // s4 <- sif (x[0:260]); stable during gemv
      for (int idx = tid; idx < NROWS * 260; idx += NTHREADS) {
        int row = idx / 260, t = idx % 260;
        s_s4[row * 260 + t] = s_x[row * 1152 + t];
      }

      gemv_small<576>(g_wh + OFFH_FW + rank * 576 * 64, s_x, 1152, PART_A);
      __syncthreads();
      if (tid < NROWS * 64) {
        int row = tid >> 6, col = tid & 63;
        exch(&s_fw[row * 256 + rank * 64 + col], tanhf(csum_small(PART_A, row, col)));
      }
      CLUSTER_SYNC_();

      gemv_small<256>(g_wh + OFFH_FWGLU + rank * 256 * 64, s_fw, 256, PART_A);
      __syncthreads();
      if (tid < NROWS * 64) {
        int row = tid >> 6, col = tid & 63;
        int j = rank * 64 + col;
        float v = s_fw[row * 256 + j] * sigmoidf_(csum_small(PART_A, row, col));
        exch(&s_fw2[row * 256 + j], v);
      }
      CLUSTER_SYNC_();

      // ---- pg: 16 warps (row, gate)
      if (tid < NROWS * 128) {
        int w = tid >> 5, l = tid & 31;
        int row = w >> 2, g = w & 3;
        float d = 0.f;
        for (int k = l; k < 256; k += 32)
          d = fmaf(s_fw2[row * 256 + k], pg_w[g * 256 + k], d);
#pragma unroll
        for (int o = 16; o; o >>= 1) d += __shfl_xor_sync(0xffffffffu, d, o);
        if (l == 0) s_pg[row * 4 + g] = sigmoidf_(d + pg_b[g]) + 1e-5f;
      }
      __syncthreads();

      // ================= GRU + GLU macros =================
#define GRU_STAGE(SRC, OFF_IH, OFF_HH, SSTATE, PGI)                              \
      for (int idx = tid; idx < NROWS * 384; idx += NTHREADS) {                  \
        int row = idx / 384, p = idx % 384;                                      \
        float v;                                                                 \
        if (p < 256)       v = SRC[row * 256 + p];                               \
        else if (p < 320)  v = s_pg[row * 4 + PGI] * s_pl[row * 68 + 2 + (p - 256)]; \
        else               v = s_psub[row * 64 + (p - 320)];                     \
        s_x[row * 1152 + p] = v;                                                 \
      }                                                                          \
      __syncthreads();                                                           \
      gemv_gru(g_wh + OFF_IH + rank * 384 * 192,                                 \
               g_wh + OFF_HH + rank * 256 * 192,                                 \
               s_x, 1152, SSTATE, PART_A, PART_B);                               \
      __syncthreads();                                                           \
      for (int idx = tid; idx < 2 * NROWS * 192; idx += NTHREADS) {              \
        int half = idx / (NROWS * 192), t = idx % (NROWS * 192);                 \
        int row = t / 192, c = t % 192;                                          \
        float v = csum_gru(half ? PART_B : PART_A, row, c);                      \
        (half ? s_hg : s_xg)[row * 192 + c] = v;                                 \
      }                                                                          \
      __syncthreads();                                                           \
      if (tid < NROWS * 64) {                                                    \
        int row = tid >> 6, sl = tid & 63;                                       \
        float r = sigmoidf_(s_xg[row * 192 + sl]      + s_hg[row * 192 + sl]);   \
        float z = sigmoidf_(s_xg[row * 192 + 64 + sl] + s_hg[row * 192 + 64 + sl]); \
        float n = tanhf(s_xg[row * 192 + 128 + sl] + r * s_hg[row * 192 + 128 + sl]); \
        int j = rank * 64 + sl;                                                  \
        float v = (1.f - z) * n + z * SSTATE[row * 256 + j];                     \
        exch(&SSTATE[row * 256 + j], v);                                         \
      }                                                                          \
      CLUSTER_SYNC_();

#define GLU_STAGE(OFF_GLU, SSTATE, DST)                                          \
      gemv_small<256>(g_wh + OFF_GLU + rank * 256 * 64, SSTATE, 256, PART_A);    \
      __syncthreads();                                                           \
      if (tid < NROWS * 64) {                                                    \
        int row = tid >> 6, col = tid & 63;                                      \
        int j = rank * 64 + col;                                                 \
        float v = SSTATE[row * 256 + j] * sigmoidf_(csum_small(PART_A, row, col)); \
        exch(&DST[row * 256 + j], v);                                            \
      }                                                                          \
      CLUSTER_SYNC_();

      GRU_STAGE(s_fw2, OFFH_G1IH, OFFH_G1HH, s_s1, 0)
      GLU_STAGE(OFFH_GLU1, s_s1, s_o1)
      GRU_STAGE(s_o1, OFFH_G2IH, OFFH_G2HH, s_s2, 1)
      GLU_STAGE(OFFH_GLU2, s_s2, s_o2)
      GRU_STAGE(s_o2, OFFH_G3IH, OFFH_G3HH, s_s3, 2)
      GLU_STAGE(OFFH_GLU3, s_s3, s_o3)
#undef GRU_STAGE
#undef GLU_STAGE

      // ---- skip input: per row [o1,o2,o3,fw2,pg3*pl2,psub] = 1152
      for (int idx = tid; idx < NROWS * 1152; idx += NTHREADS) {
        int row = idx / 1152, p = idx % 1152;
        float v;
        if (p < 256)        v = s_o1[row * 256 + p];
        else if (p < 512)   v = s_o2[row * 256 + (p - 256)];
        else if (p < 768)   v = s_o3[row * 256 + (p - 512)];
        else if (p < 1024)  v = s_fw2[row * 256 + (p - 768)];
        else if (p < 1088)  v = s_pg[row * 4 + 3] * s_pl[row * 68 + 2 + (p - 1024)];
        else                v = s_psub[row * 64 + (p - 1088)];
        s_x[row * 1152 + p] = v;
      }
      __syncthreads();
      gemv_small<1152>(g_wh + OFFH_SKIP + rank * 1152 * 64, s_x, 1152, PART_A);
      __syncthreads();
      if (tid < NROWS * 64) {
        int row = tid >> 6, col = tid & 63;
        exch(&s_sk[row * 256 + rank * 64 + col], tanhf(csum_small(PART_A, row, col)));
      }
      CLUSTER_SYNC_();

      gemv_small<256>(g_wh + OFFH_SKIPGLU + rank * 256 * 64, s_sk, 256, PART_A);
      __syncthreads();
      if (tid < NROWS * 64) {
        int row = tid >> 6, col = tid & 63;
        int j = rank * 64 + col;
        float v = s_sk[row * 256 + j] * sigmoidf_(csum_small(PART_A, row, col));
        exch(&s_sk2[row * 256 + j], v);
      }
      CLUSTER_SYNC_();

      // ---- out: warp w -> row = w&3, outputs rank*16 + (w>>2)*2 + {0,1}
      {
        const int w = tid >> 5, lane = tid & 31;
        const int row = w & 3, og = w >> 2;
        const int o = rank * 16 + og * 2 + (lane >> 4);
        const int l = lane & 15;
        const float4* wr = reinterpret_cast<const float4*>(out_w + o * 256) + l * 4;
        const float4* xr = reinterpret_cast<const float4*>(s_sk2 + row * 256) + l * 4;
        float d = 0.f;
#pragma unroll
        for (int j = 0; j < 4; ++j) {
          float4 wa = wr[j], xa = xr[j];
          d += wa.x * xa.x + wa.y * xa.y + wa.z * xa.z + wa.w * xa.w;
        }
#pragma unroll
        for (int m = 1; m <= 8; m <<= 1) d += __shfl_xor_sync(0xffffffffu, d, m);
        if (l == 0) {
          float v = tanhf(d) * s_gain[row * 2];
          exch(&s_out[row * 64 + o], v);
          outp[(q * NROWS + row) * 25600 + f * 256 + i * 64 + o] = v;
        }
      }
      CLUSTER_SYNC_();

      // ---- prev = [prev[64:], out] per row
      float pv;
      {
        int row = tid >> 8, t = tid & 255;
        pv = (t < 192) ? s_prev[row * 256 + t + 64] : s_out[row * 64 + (t - 192)];
      }
      __syncthreads();
      s_prev[tid] = pv;
      __syncthreads();
    }
  }
}

// ---------------------------------------------------------------------------
extern "C" void kernel_launch(void* const* d_in, const int* in_sizes, int n_in,
                              void* d_out, int out_size) {
  (void)in_sizes; (void)n_in; (void)out_size;
  const float* features = (const float*)d_in[0];
  const float* gfeat    = (const float*)d_in[1];
  const float* prev     = (const float*)d_in[2];
  const int*   periods  = (const int*)d_in[3];
  const float* cond_w1  = (const float*)d_in[4];
  const float* cond_w2  = (const float*)d_in[5];
  const float* cond_w3  = (const float*)d_in[6];
  const float* gain_w   = (const float*)d_in[7];
  const float* gain_b   = (const float*)d_in[8];
  const float* fw_w     = (const float*)d_in[9];
  const float* fw_glu_w = (const float*)d_in[10];
  const float* pg_w     = (const float*)d_in[11];
  const float* pg_b     = (const float*)d_in[12];
  const float* g1ih     = (const float*)d_in[13];
  const float* g1hh     = (const float*)d_in[14];
  const float* g2ih     = (const float*)d_in[15];
  const float* g2hh     = (const float*)d_in[16];
  const float* g3ih     = (const float*)d_in[17];
  const float* g3hh     = (const float*)d_in[18];
  const float* glu1     = (const float*)d_in[19];
  const float* glu2     = (const float*)d_in[20];
  const float* glu3     = (const float*)d_in[21];
  const float* skip_w   = (const float*)d_in[22];
  const float* skipglu  = (const float*)d_in[23];
  const float* out_w    = (const float*)d_in[24];

  __half* wh = nullptr;
  float*  wc = nullptr;
  cudaGetSymbolAddress((void**)&wh, g_wh);
  cudaGetSymbolAddress((void**)&wc, g_wc);

  auto rg4 = [&](const float* src, int off, int O, int I, int Ipad) {
    int tot = O * Ipad;
    reorg_h4<<<(tot + 255) / 256, 256>>>(src, wh + off, O, I, Ipad);
  };
  auto rgg = [&](const float* src, int off, int I) {
    int tot = 768 * I;
    reorg_gru4<<<(tot + 255) / 256, 256>>>(src, wh + off, I);
  };
  auto tpc = [&](const float* src, int off, int O, int I) {
    int tot = O * I;
    transpose_k<<<(tot + 255) / 256, 256>>>(src, wc + off, O, I);
  };

  rg4(fw_w,     OFFH_FW,      256, 520, 576);
  rg4(fw_glu_w, OFFH_FWGLU,   256, 256, 256);
  rgg(g1ih,     OFFH_G1IH,    384);
  rgg(g1hh,     OFFH_G1HH,    256);
  rgg(g2ih,     OFFH_G2IH,    384);
  rgg(g2hh,     OFFH_G2HH,    256);
  rgg(g3ih,     OFFH_G3IH,    384);
  rgg(g3hh,     OFFH_G3HH,    256);
  rg4(glu1,     OFFH_GLU1,    256, 256, 256);
  rg4(glu2,     OFFH_GLU2,    256, 256, 256);
  rg4(glu3,     OFFH_GLU3,    256, 256, 256);
  rg4(skip_w,   OFFH_SKIP,    256, 1152, 1152);
  rg4(skipglu,  OFFH_SKIPGLU, 256, 256, 256);
  tpc(cond_w1,  OFFC_C1,      336, 336);
  tpc(cond_w2,  OFFC_C2,      336, 336);
  tpc(cond_w3,  OFFC_C3,      512, 336);

  dim3 cg(NB, NFRAMES);
  cond_kernel<<<cg, 256>>>(features, gfeat);

  const int dyn_smem = DO_TOTAL * (int)sizeof(float);  // ~171 KB
  cudaFuncSetAttribute(main_kernel, cudaFuncAttributeMaxDynamicSharedMemorySize, dyn_smem);
  main_kernel<<<16 * CLSZ, NTHREADS, dyn_smem>>>(prev, periods, gain_w, gain_b,
                                                 pg_w, pg_b, out_w, (float*)d_out);
}

// round 13
// speedup vs baseline: 2.0230x; 1.4101x over previous
#include <cuda_runtime.h>
#include <cuda_fp16.h>
#include <stdint.h>
#include <math.h>

// ----------------------------------------------------------------------------
// FARGAN vocoder. Round 12: proven Round-7 topology (4-CTA clusters, 2 batch
// rows per cluster, 32 clusters x 4 = 128 CTAs; weights reused for 2 rows).
// Changes vs R7: GRU csum vectorized to float4 (4x fewer LDS warp-instrs),
// gemv unrolls deepened. fp16 K-major weights, fp32 accumulate.
// ----------------------------------------------------------------------------

#define NFRAMES 100
#define NB      64
#define NTHREADS 1024

__device__ __forceinline__ float sigmoidf_(float x) { return 1.0f / (1.0f + expf(-x)); }

__device__ __forceinline__ uint32_t s2u_(const void* p) {
  uint32_t a;
  asm("{ .reg .u64 t; cvta.to.shared.u64 t, %1; cvt.u32.u64 %0, t; }" : "=r"(a) : "l"(p));
  return a;
}
__device__ __forceinline__ uint32_t mapa_u_(uint32_t a, uint32_t r) {
  uint32_t d;
  asm("mapa.shared::cluster.u32 %0, %1, %2;" : "=r"(d) : "r"(a), "r"(r));
  return d;
}
__device__ __forceinline__ void st_peer_(uint32_t a, float v) {
  asm volatile("st.shared::cluster.f32 [%0], %1;" :: "r"(a), "f"(v));
}
#define CLUSTER_SYNC_() do { \
  asm volatile("barrier.cluster.arrive.aligned;" ::: "memory"); \
  asm volatile("barrier.cluster.wait.aligned;" ::: "memory"); \
} while (0)

// fp16 weights, 4 rank-slices per matrix: [4][Kpad][Oq]
enum : int {
  OFFH_FW      = 0,                          // 4 x 544 x 64
  OFFH_FWGLU   = OFFH_FW      + 544 * 256,   // 4 x 256 x 64
  OFFH_G1IH    = OFFH_FWGLU   + 256 * 256,   // 4 x 384 x 192
  OFFH_G1HH    = OFFH_G1IH    + 384 * 768,   // 4 x 256 x 192
  OFFH_G2IH    = OFFH_G1HH    + 256 * 768,
  OFFH_G2HH    = OFFH_G2IH    + 384 * 768,
  OFFH_G3IH    = OFFH_G2HH    + 256 * 768,
  OFFH_G3HH    = OFFH_G3IH    + 384 * 768,
  OFFH_GLU1    = OFFH_G3HH    + 256 * 768,
  OFFH_GLU2    = OFFH_GLU1    + 256 * 256,
  OFFH_GLU3    = OFFH_GLU2    + 256 * 256,
  OFFH_SKIP    = OFFH_GLU3    + 256 * 256,   // 4 x 1152 x 64
  OFFH_SKIPGLU = OFFH_SKIP    + 1152 * 256,
  WH_TOTAL     = OFFH_SKIPGLU + 256 * 256
};

enum : int {
  OFFC_C1  = 0,
  OFFC_C2  = OFFC_C1 + 336 * 336,
  OFFC_C3  = OFFC_C2 + 336 * 336,
  WC_TOTAL = OFFC_C3 + 336 * 512
};

__device__ __half g_wh[WH_TOTAL];
__device__ float  g_wc[WC_TOTAL];
__device__ float  g_cond[NFRAMES * NB * 512];

// ---------------------------------------------------------------------------
__global__ void transpose_k(const float* __restrict__ src, float* __restrict__ dst,
                            int O, int I) {
  int idx = blockIdx.x * blockDim.x + threadIdx.x;
  if (idx < O * I) {
    int i = idx / O;
    int o = idx % O;
    dst[idx] = src[o * I + i];
  }
}

// 4-way mode0 reorg: src[O][I] -> dst[4][Ipad][O/4] fp16
__global__ void reorg_h4(const float* __restrict__ src, __half* __restrict__ dst,
                         int O, int I, int Ipad) {
  int idx = blockIdx.x * blockDim.x + threadIdx.x;
  if (idx >= O * Ipad) return;
  int i = idx / O, o = idx % O;
  int Oq = O >> 2;
  int r = o / Oq, c = o % Oq;
  float v = (i < I) ? src[o * I + i] : 0.f;
  dst[((size_t)r * Ipad + i) * Oq + c] = __float2half(v);
}

// 4-way GRU reorg (gate-permuted): w[768][I] -> dst[4][I][192]
// s=o%256, g=o/256; rank=s/64; col=g*64+(s%64)
__global__ void reorg_gru4(const float* __restrict__ src, __half* __restrict__ dst,
                           int I) {
  int idx = blockIdx.x * blockDim.x + threadIdx.x;
  if (idx >= 768 * I) return;
  int i = idx / 768, o = idx % 768;
  int s = o & 255, g = o >> 8;
  int r = s >> 6, c = g * 64 + (s & 63);
  dst[((size_t)r * I + i) * 192 + c] = __float2half(src[o * I + i]);
}

// ---------------------------------------------------------------------------
// 2-row fp16 GEMV partial, 1024 thr = 32 K-chunks x 32 lanes, float2 weights.
// NQ==64: lane = row*16 + v (16 float2 cols per row). NQ==192: both rows,
// groups v=lane and v=32+lane (lane<16). part[(row*32+kc)*NQ + col].
template <int K, int NQ>
__device__ __forceinline__ void gemv2r(const __half* __restrict__ Wh,
                                       const float* __restrict__ xs, int rs,
                                       float* __restrict__ part) {
  const int tid  = threadIdx.x;
  const int kc   = tid >> 5;
  const int lane = tid & 31;
  constexpr int Kc  = K / 32;
  constexpr int NV2 = NQ / 4;
  const float2* __restrict__ W2 =
      reinterpret_cast<const float2*>(Wh) + (size_t)(kc * Kc) * NV2;

  if (NQ == 64) {
    const int row = lane >> 4, v = lane & 15;
    const float* xk = xs + row * rs + kc * Kc;
    float acc[4] = {0.f, 0.f, 0.f, 0.f};
#pragma unroll 8
    for (int k = 0; k < Kc; ++k) {
      const float xv = xk[k];
      float2 hw = W2[k * 16 + v];
      const __half2* hp = reinterpret_cast<const __half2*>(&hw);
      float2 f0 = __half22float2(hp[0]);
      float2 f1 = __half22float2(hp[1]);
      acc[0] = fmaf(xv, f0.x, acc[0]);
      acc[1] = fmaf(xv, f0.y, acc[1]);
      acc[2] = fmaf(xv, f1.x, acc[2]);
      acc[3] = fmaf(xv, f1.y, acc[3]);
    }
    float4* P4 = reinterpret_cast<float4*>(part + (row * 32 + kc) * 64);
    P4[v] = make_float4(acc[0], acc[1], acc[2], acc[3]);
  } else {  // NQ == 192
    const float* xk0 = xs + kc * Kc;
    const float* xk1 = xs + rs + kc * Kc;
    float a0[2][4], a1[2][4];
#pragma unroll
    for (int j = 0; j < 4; ++j) { a0[0][j] = a0[1][j] = a1[0][j] = a1[1][j] = 0.f; }
#pragma unroll
    for (int k = 0; k < Kc; ++k) {
      const float x0 = xk0[k], x1 = xk1[k];
      float2 hwa = W2[k * 48 + lane];
      const __half2* hpa = reinterpret_cast<const __half2*>(&hwa);
      float2 fa0 = __half22float2(hpa[0]);
      float2 fa1 = __half22float2(hpa[1]);
      a0[0][0] = fmaf(x0, fa0.x, a0[0][0]); a0[0][1] = fmaf(x0, fa0.y, a0[0][1]);
      a0[0][2] = fmaf(x0, fa1.x, a0[0][2]); a0[0][3] = fmaf(x0, fa1.y, a0[0][3]);
      a0[1][0] = fmaf(x1, fa0.x, a0[1][0]); a0[1][1] = fmaf(x1, fa0.y, a0[1][1]);
      a0[1][2] = fmaf(x1, fa1.x, a0[1][2]); a0[1][3] = fmaf(x1, fa1.y, a0[1][3]);
      if (lane < 16) {
        float2 hwb = W2[k * 48 + 32 + lane];
        const __half2* hpb = reinterpret_cast<const __half2*>(&hwb);
        float2 fb0 = __half22float2(hpb[0]);
        float2 fb1 = __half22float2(hpb[1]);
        a1[0][0] = fmaf(x0, fb0.x, a1[0][0]); a1[0][1] = fmaf(x0, fb0.y, a1[0][1]);
        a1[0][2] = fmaf(x0, fb1.x, a1[0][2]); a1[0][3] = fmaf(x0, fb1.y, a1[0][3]);
        a1[1][0] = fmaf(x1, fb0.x, a1[1][0]); a1[1][1] = fmaf(x1, fb0.y, a1[1][1]);
        a1[1][2] = fmaf(x1, fb1.x, a1[1][2]); a1[1][3] = fmaf(x1, fb1.y, a1[1][3]);
      }
    }
#pragma unroll
    for (int row = 0; row < 2; ++row) {
      float4* P4 = reinterpret_cast<float4*>(part + (row * 32 + kc) * 192);
      P4[lane] = make_float4(a0[row][0], a0[row][1], a0[row][2], a0[row][3]);
      if (lane < 16)
        P4[32 + lane] = make_float4(a1[row][0], a1[row][1], a1[row][2], a1[row][3]);
    }
  }
}

__device__ __forceinline__ float csum2r(const float* __restrict__ part, int NQ,
                                        int row, int j) {
  const float* p = part + (row * 32) * NQ + j;
  float s = 0.f;
#pragma unroll
  for (int c = 0; c < 32; c += 4) {
    float a = p[c * NQ]       + p[(c + 1) * NQ];
    float b = p[(c + 2) * NQ] + p[(c + 3) * NQ];
    s += (a + b);
  }
  return s;
}

// ---------------------------------------------------------------------------
// conditioning net (unchanged)
__device__ __forceinline__ void gemv_part(const float* __restrict__ Wt,
                                          const float* __restrict__ xs,
                                          int K, int N, float* part) {
  const int tid = threadIdx.x;
  const int kc  = tid >> 6;
  const int g0  = tid & 63;
  const int Kc  = K >> 2;
  const int G   = N >> 2;
  const float4* __restrict__ W4 = reinterpret_cast<const float4*>(Wt) + (size_t)(kc * Kc) * G;
  const float*  __restrict__ xk = xs + kc * Kc;
  float4* P4 = reinterpret_cast<float4*>(part + kc * N);
  for (int g = g0; g < G; g += 64) {
    float4 acc = make_float4(0.f, 0.f, 0.f, 0.f);
    const float4* wp = W4 + g;
#pragma unroll 4
    for (int k = 0; k < Kc; ++k) {
      const float xv = xk[k];
      const float4 w = wp[(size_t)k * G];
      acc.x = fmaf(xv, w.x, acc.x);
      acc.y = fmaf(xv, w.y, acc.y);
      acc.z = fmaf(xv, w.z, acc.z);
      acc.w = fmaf(xv, w.w, acc.w);
    }
    P4[g] = acc;
  }
}
__device__ __forceinline__ float csum4(const float* part, int N, int j) {
  return (part[j] + part[N + j]) + (part[2 * N + j] + part[3 * N + j]);
}

__global__ __launch_bounds__(256)
void cond_kernel(const float* __restrict__ feat, const float* __restrict__ gf) {
  __shared__ __align__(16) float s_part[4 * 512];
  __shared__ float s_x[336];
  __shared__ float s_y[336];
  const int b = blockIdx.x, f = blockIdx.y, tid = threadIdx.x;

  for (int j = tid; j < 80; j += 256)  s_x[j]      = feat[(b * 80 + j) * NFRAMES + f];
  for (int j = tid; j < 256; j += 256) s_x[80 + j] = gf[b * 256 + j];
  __syncthreads();
  gemv_part(g_wc + OFFC_C1, s_x, 336, 336, s_part);
  __syncthreads();
  for (int j = tid; j < 336; j += 256) s_y[j] = tanhf(csum4(s_part, 336, j));
  __syncthreads();
  gemv_part(g_wc + OFFC_C2, s_y, 336, 336, s_part);
  __syncthreads();
  for (int j = tid; j < 336; j += 256) s_x[j] = tanhf(csum4(s_part, 336, j));
  __syncthreads();
  gemv_part(g_wc + OFFC_C3, s_x, 336, 512, s_part);
  __syncthreads();
  float* dst = g_cond + (f * NB + b) * 512;
  for (int j = tid; j < 512; j += 256) dst[j] = tanhf(csum4(s_part, 512, j));
}

// ---------------------------------------------------------------------------
// main kernel: 32 clusters of 4 CTAs; cluster q handles rows 2q, 2q+1.
// dynamic smem: partA[2*32*192] + partB[2*32*192] floats (96 KB)
extern __shared__ float s_dyn[];
#define PART_A (s_dyn)
#define PART_B (s_dyn + 2 * 32 * 192)

__global__ __launch_bounds__(NTHREADS, 1) __cluster_dims__(4, 1, 1)
void main_kernel(const float* __restrict__ prev0,
                 const int*   __restrict__ periods,
                 const float* __restrict__ gain_w,
                 const float* __restrict__ gain_b,
                 const float* __restrict__ pg_w,
                 const float* __restrict__ pg_b,
                 const float* __restrict__ out_w,
                 float*       __restrict__ outp) {
  __shared__ float s_x[2 * 1152];
  __shared__ __align__(16) float s_xg[2 * 192];
  __shared__ __align__(16) float s_hg[2 * 192];
  __shared__ float s_prev[2 * 256], s_s1[2 * 256], s_s2[2 * 256], s_s3[2 * 256];
  __shared__ float s_s4[2 * 260];
  __shared__ float s_fw[2 * 256], s_fw2[2 * 256];
  __shared__ float s_o1[2 * 256], s_o2[2 * 256], s_o3[2 * 256];
  __shared__ float s_sk[2 * 256], s_sk2[2 * 256];
  __shared__ float s_pl[2 * 68], s_psub[2 * 64], s_pg[2 * 4], s_gain[2 * 2];
  __shared__ float s_out[2 * 64];

  const int tid  = threadIdx.x;
  const int rank = blockIdx.x & 3;
  const int q    = blockIdx.x >> 2;

  // exchange helper: write v to own smem + 3 peers at same offset
  auto exch = [&](float* addr, float v) {
    *addr = v;
    uint32_t a = s2u_(addr);
    st_peer_(mapa_u_(a, (rank + 1) & 3), v);
    st_peer_(mapa_u_(a, (rank + 2) & 3), v);
    st_peer_(mapa_u_(a, (rank + 3) & 3), v);
  };

  if (tid < 512) {
    s_prev[tid] = prev0[q * 512 + tid];
    s_s1[tid] = 0.f; s_s2[tid] = 0.f; s_s3[tid] = 0.f;
  }
  if (tid < 520) s_s4[tid] = 0.f;
  __syncthreads();

  const float gb0 = gain_b[0];
  int per[2];
  const float* condr[2];

  for (int f = 0; f < NFRAMES; ++f) {
    per[0] = periods[(q * 2 + 0) * NFRAMES + f];
    per[1] = periods[(q * 2 + 1) * NFRAMES + f];
    condr[0] = g_cond + (f * NB + q * 2 + 0) * 512;
    condr[1] = g_cond + (f * NB + q * 2 + 1) * 512;

    for (int i = 0; i < 4; ++i) {
      // ---- gain: warp r computes row r (redundant across CTAs)
      if (tid < 64) {
        int row = tid >> 5, l = tid & 31;
        const float* sf = condr[row] + i * 128;
        float d = 0.f;
        for (int k = l; k < 128; k += 32) d = fmaf(sf[k], gain_w[k], d);
#pragma unroll
        for (int o = 16; o; o >>= 1) d += __shfl_xor_sync(0xffffffffu, d, o);
        if (l == 0) {
          float g = expf(d + gb0);
          s_gain[row * 2]     = g;
          s_gain[row * 2 + 1] = 1.0f / (1e-5f + g);
        }
      }
      __syncthreads();

      // ---- pitch gather + psub per row
      if (tid < 136) {
        int row = tid / 68, t = tid % 68;
        int idx = 256 - per[row] + t - 2;
        if (idx >= 256) idx -= per[row];
        s_pl[row * 68 + t] = s_prev[row * 256 + idx] * s_gain[row * 2 + 1];
      } else if (tid >= 256 && tid < 384) {
        int row = (tid - 256) >> 6, t = (tid - 256) & 63;
        s_psub[row * 64 + t] = s_prev[row * 256 + 192 + t] * s_gain[row * 2 + 1];
      }
      __syncthreads();

      // ---- fw input assembly: per row [sf(128), psub(64), pl(68), s4(260), pad]
      for (int idx = tid; idx < 2 * 544; idx += NTHREADS) {
        int row = idx / 544, p = idx % 544;
        float v;
        if (p < 128)       v = condr[row][i * 128 + p];
        else if (p < 192)  v = s_psub[row * 64 + (p - 128)];
        else if (p < 260)  v = s_pl[row * 68 + (p - 192)];
        else if (p < 520)  v = s_s4[row * 260 + (p - 260)];
        else               v = 0.f;
        s_x[row * 1152 + p] = v;
      }
      __syncthreads();
      // s4 <- sif (x[0:260]); stable during gemv
      if (tid < 520) {
        int row = tid / 260, t = tid % 260;
        s_s4[row * 260 + t] = s_x[row * 1152 + t];
      }

      gemv2r<544, 64>(g_wh + OFFH_FW + rank * 544 * 64, s_x, 1152, PART_A);
      __syncthreads();
      if (tid < 128) {
        int row = tid >> 6, jl = tid & 63;
        exch(&s_fw[row * 256 + rank * 64 + jl], tanhf(csum2r(PART_A, 64, row, jl)));
      }
      CLUSTER_SYNC_();

      gemv2r<256, 64>(g_wh + OFFH_FWGLU + rank * 256 * 64, s_fw, 256, PART_A);
      __syncthreads();
      if (tid < 128) {
        int row = tid >> 6, jl = tid & 63;
        int j = rank * 64 + jl;
        float v = s_fw[row * 256 + j] * sigmoidf_(csum2r(PART_A, 64, row, jl));
        exch(&s_fw2[row * 256 + j], v);
      }
      CLUSTER_SYNC_();

      // ---- pg: 8 warps (row, gate) redundant per CTA
      if (tid < 256) {
        int w = tid >> 5, l = tid & 31;
        int row = w >> 2, g = w & 3;
        float d = 0.f;
        for (int k = l; k < 256; k += 32)
          d = fmaf(s_fw2[row * 256 + k], pg_w[g * 256 + k], d);
#pragma unroll
        for (int o = 16; o; o >>= 1) d += __shfl_xor_sync(0xffffffffu, d, o);
        if (l == 0) s_pg[row * 4 + g] = sigmoidf_(d + pg_b[g]) + 1e-5f;
      }
      __syncthreads();

      // ================= GRU + GLU macros =================
#define GRU_STAGE(SRC, OFF_IH, OFF_HH, SSTATE, PGI)                              \
      for (int idx = tid; idx < 2 * 384; idx += NTHREADS) {                      \
        int row = idx / 384, p = idx % 384;                                      \
        float v;                                                                 \
        if (p < 256)       v = SRC[row * 256 + p];                               \
        else if (p < 320)  v = s_pg[row * 4 + PGI] * s_pl[row * 68 + 2 + (p - 256)]; \
        else               v = s_psub[row * 64 + (p - 320)];                     \
        s_x[row * 1152 + p] = v;                                                 \
      }                                                                          \
      __syncthreads();                                                           \
      gemv2r<384, 192>(g_wh + OFF_IH + rank * 384 * 192, s_x, 1152, PART_A);     \
      gemv2r<256, 192>(g_wh + OFF_HH + rank * 256 * 192, SSTATE, 256, PART_B);   \
      __syncthreads();                                                           \
      if (tid < 192) {                                                           \
        int arr = tid / 96, t = tid % 96;                                        \
        int row = t / 48, g4 = t % 48;                                           \
        const float* p = (arr ? PART_B : PART_A) + row * 32 * 192 + g4 * 4;      \
        float4 u0 = make_float4(0.f, 0.f, 0.f, 0.f);                             \
        float4 u1 = make_float4(0.f, 0.f, 0.f, 0.f);                             \
        _Pragma("unroll")                                                        \
        for (int c = 0; c < 32; c += 2) {                                        \
          float4 va = *reinterpret_cast<const float4*>(p + c * 192);             \
          float4 vb = *reinterpret_cast<const float4*>(p + (c + 1) * 192);       \
          u0.x += va.x; u0.y += va.y; u0.z += va.z; u0.w += va.w;                \
          u1.x += vb.x; u1.y += vb.y; u1.z += vb.z; u1.w += vb.w;                \
        }                                                                        \
        float4 s = make_float4(u0.x + u1.x, u0.y + u1.y, u0.z + u1.z, u0.w + u1.w); \
        *reinterpret_cast<float4*>((arr ? s_hg : s_xg) + row * 192 + g4 * 4) = s; \
      }                                                                          \
      __syncthreads();                                                           \
      if (tid < 128) {                                                           \
        int row = tid >> 6, sl = tid & 63;                                       \
        float r = sigmoidf_(s_xg[row * 192 + sl]       + s_hg[row * 192 + sl]);  \
        float z = sigmoidf_(s_xg[row * 192 + 64 + sl]  + s_hg[row * 192 + 64 + sl]); \
        float n = tanhf(s_xg[row * 192 + 128 + sl] + r * s_hg[row * 192 + 128 + sl]); \
        int j = rank * 64 + sl;                                                  \
        float v = (1.f - z) * n + z * SSTATE[row * 256 + j];                     \
        exch(&SSTATE[row * 256 + j], v);                                         \
      }                                                                          \
      CLUSTER_SYNC_();

#define GLU_STAGE(OFF_GLU, SSTATE, DST)                                          \
      gemv2r<256, 64>(g_wh + OFF_GLU + rank * 256 * 64, SSTATE, 256, PART_A);    \
      __syncthreads();                                                           \
      if (tid < 128) {                                                           \
        int row = tid >> 6, jl = tid & 63;                                       \
        int j = rank * 64 + jl;                                                  \
        float v = SSTATE[row * 256 + j] * sigmoidf_(csum2r(PART_A, 64, row, jl)); \
        exch(&DST[row * 256 + j], v);                                            \
      }                                                                          \
      CLUSTER_SYNC_();

      GRU_STAGE(s_fw2, OFFH_G1IH, OFFH_G1HH, s_s1, 0)
      GLU_STAGE(OFFH_GLU1, s_s1, s_o1)
      GRU_STAGE(s_o1, OFFH_G2IH, OFFH_G2HH, s_s2, 1)
      GLU_STAGE(OFFH_GLU2, s_s2, s_o2)
      GRU_STAGE(s_o2, OFFH_G3IH, OFFH_G3HH, s_s3, 2)
      GLU_STAGE(OFFH_GLU3, s_s3, s_o3)
#undef GRU_STAGE
#undef GLU_STAGE

      // ---- skip input: per row [o1,o2,o3,fw2,pg3*pl2,psub] = 1152
      for (int idx = tid; idx < 2 * 1152; idx += NTHREADS) {
        int row = idx / 1152, p = idx % 1152;
        float v;
        if (p < 256)        v = s_o1[row * 256 + p];
        else if (p < 512)   v = s_o2[row * 256 + (p - 256)];
        else if (p < 768)   v = s_o3[row * 256 + (p - 512)];
        else if (p < 1024)  v = s_fw2[row * 256 + (p - 768)];
        else if (p < 1088)  v = s_pg[row * 4 + 3] * s_pl[row * 68 + 2 + (p - 1024)];
        else                v = s_psub[row * 64 + (p - 1088)];
        s_x[row * 1152 + p] = v;
      }
      __syncthreads();
      gemv2r<1152, 64>(g_wh + OFFH_SKIP + rank * 1152 * 64, s_x, 1152, PART_A);
      __syncthreads();
      if (tid < 128) {
        int row = tid >> 6, jl = tid & 63;
        exch(&s_sk[row * 256 + rank * 64 + jl], tanhf(csum2r(PART_A, 64, row, jl)));
      }
      CLUSTER_SYNC_();

      gemv2r<256, 64>(g_wh + OFFH_SKIPGLU + rank * 256 * 64, s_sk, 256, PART_A);
      __syncthreads();
      if (tid < 128) {
        int row = tid >> 6, jl = tid & 63;
        int j = rank * 64 + jl;
        float v = s_sk[row * 256 + j] * sigmoidf_(csum2r(PART_A, 64, row, jl));
        exch(&s_sk2[row * 256 + j], v);
      }
      CLUSTER_SYNC_();

      // ---- out: warp w -> output o = rank*16 + (w>>1), row = w&1
      {
        const int w = tid >> 5, l = tid & 31;
        const int o = rank * 16 + (w >> 1), row = w & 1;
        const float4* wr = reinterpret_cast<const float4*>(out_w + o * 256) + l * 2;
        const float4* xr = reinterpret_cast<const float4*>(s_sk2 + row * 256) + l * 2;
        float4 wa = wr[0], wb = wr[1];
        float4 xa = xr[0], xb = xr[1];
        float d = wa.x * xa.x + wa.y * xa.y + wa.z * xa.z + wa.w * xa.w
                + wb.x * xb.x + wb.y * xb.y + wb.z * xb.z + wb.w * xb.w;
#pragma unroll
        for (int oo = 16; oo; oo >>= 1) d += __shfl_xor_sync(0xffffffffu, d, oo);
        if (l == 0) {
          float v = tanhf(d) * s_gain[row * 2];
          exch(&s_out[row * 64 + o], v);
          outp[(q * 2 + row) * 25600 + f * 256 + i * 64 + o] = v;
        }
      }
      CLUSTER_SYNC_();

      // ---- prev = [prev[64:], out] per row
      float pv = 0.f;
      if (tid < 512) {
        int row = tid >> 8, t = tid & 255;
        pv = (t < 192) ? s_prev[row * 256 + t + 64] : s_out[row * 64 + (t - 192)];
      }
      __syncthreads();
      if (tid < 512) s_prev[tid] = pv;
      __syncthreads();
    }
  }
}

// ---------------------------------------------------------------------------
extern "C" void kernel_launch(void* const* d_in, const int* in_sizes, int n_in,
                              void* d_out, int out_size) {
  (void)in_sizes; (void)n_in; (void)out_size;
  const float* features = (const float*)d_in[0];
  const float* gfeat    = (const float*)d_in[1];
  const float* prev     = (const float*)d_in[2];
  const int*   periods  = (const int*)d_in[3];
  const float* cond_w1  = (const float*)d_in[4];
  const float* cond_w2  = (const float*)d_in[5];
  const float* cond_w3  = (const float*)d_in[6];
  const float* gain_w   = (const float*)d_in[7];
  const float* gain_b   = (const float*)d_in[8];
  const float* fw_w     = (const float*)d_in[9];
  const float* fw_glu_w = (const float*)d_in[10];
  const float* pg_w     = (const float*)d_in[11];
  const float* pg_b     = (const float*)d_in[12];
  const float* g1ih     = (const float*)d_in[13];
  const float* g1hh     = (const float*)d_in[14];
  const float* g2ih     = (const float*)d_in[15];
  const float* g2hh     = (const float*)d_in[16];
  const float* g3ih     = (const float*)d_in[17];
  const float* g3hh     = (const float*)d_in[18];
  const float* glu1     = (const float*)d_in[19];
  const float* glu2     = (const float*)d_in[20];
  const float* glu3     = (const float*)d_in[21];
  const float* skip_w   = (const float*)d_in[22];
  const float* skipglu  = (const float*)d_in[23];
  const float* out_w    = (const float*)d_in[24];

  __half* wh = nullptr;
  float*  wc = nullptr;
  cudaGetSymbolAddress((void**)&wh, g_wh);
  cudaGetSymbolAddress((void**)&wc, g_wc);

  auto rg4 = [&](const float* src, int off, int O, int I, int Ipad) {
    int tot = O * Ipad;
    reorg_h4<<<(tot + 255) / 256, 256>>>(src, wh + off, O, I, Ipad);
  };
  auto rgg = [&](const float* src, int off, int I) {
    int tot = 768 * I;
    reorg_gru4<<<(tot + 255) / 256, 256>>>(src, wh + off, I);
  };
  auto tpc = [&](const float* src, int off, int O, int I) {
    int tot = O * I;
    transpose_k<<<(tot + 255) / 256, 256>>>(src, wc + off, O, I);
  };

  rg4(fw_w,     OFFH_FW,      256, 520, 544);
  rg4(fw_glu_w, OFFH_FWGLU,   256, 256, 256);
  rgg(g1ih,     OFFH_G1IH,    384);
  rgg(g1hh,     OFFH_G1HH,    256);
  rgg(g2ih,     OFFH_G2IH,    384);
  rgg(g2hh,     OFFH_G2HH,    256);
  rgg(g3ih,     OFFH_G3IH,    384);
  rgg(g3hh,     OFFH_G3HH,    256);
  rg4(glu1,     OFFH_GLU1,    256, 256, 256);
  rg4(glu2,     OFFH_GLU2,    256, 256, 256);
  rg4(glu3,     OFFH_GLU3,    256, 256, 256);
  rg4(skip_w,   OFFH_SKIP,    256, 1152, 1152);
  rg4(skipglu,  OFFH_SKIPGLU, 256, 256, 256);
  tpc(cond_w1,  OFFC_C1,      336, 336);
  tpc(cond_w2,  OFFC_C2,      336, 336);
  tpc(cond_w3,  OFFC_C3,      512, 336);

  dim3 cg(NB, NFRAMES);
  cond_kernel<<<cg, 256>>>(features, gfeat);

  const int dyn_smem = 2 * 2 * 32 * 192 * (int)sizeof(float);  // 96 KB
  cudaFuncSetAttribute(main_kernel, cudaFuncAttributeMaxDynamicSharedMemorySize, dyn_smem);
  main_kernel<<<128, NTHREADS, dyn_smem>>>(prev, periods, gain_w, gain_b,
                                           pg_w, pg_b, out_w, (float*)d_out);
}

// round 14
// speedup vs baseline: 2.0432x; 1.0100x over previous
#include <cuda_runtime.h>
#include <cuda_fp16.h>
#include <stdint.h>
#include <math.h>

// ----------------------------------------------------------------------------
// FARGAN vocoder. Round 13: R12 topology (4-CTA clusters, 2 rows/cluster,
// 128 CTAs) + HH-hoisting: the three GRU HH gemvs (inputs s1/s2/s3 pre-update,
// known at subframe start) run concurrently with the fw gemv in one fat head
// phase on disjoint warp groups. GRU phases become IH-only. fp16 weights.
// ----------------------------------------------------------------------------

#define NFRAMES 100
#define NB      64
#define NTHREADS 1024

__device__ __forceinline__ float sigmoidf_(float x) { return 1.0f / (1.0f + expf(-x)); }

__device__ __forceinline__ uint32_t s2u_(const void* p) {
  uint32_t a;
  asm("{ .reg .u64 t; cvta.to.shared.u64 t, %1; cvt.u32.u64 %0, t; }" : "=r"(a) : "l"(p));
  return a;
}
__device__ __forceinline__ uint32_t mapa_u_(uint32_t a, uint32_t r) {
  uint32_t d;
  asm("mapa.shared::cluster.u32 %0, %1, %2;" : "=r"(d) : "r"(a), "r"(r));
  return d;
}
__device__ __forceinline__ void st_peer_(uint32_t a, float v) {
  asm volatile("st.shared::cluster.f32 [%0], %1;" :: "r"(a), "f"(v));
}
#define CLUSTER_SYNC_() do { \
  asm volatile("barrier.cluster.arrive.aligned;" ::: "memory"); \
  asm volatile("barrier.cluster.wait.aligned;" ::: "memory"); \
} while (0)

// fp16 weights, 4 rank-slices per matrix: [4][Kpad][Oq]
enum : int {
  OFFH_FW      = 0,                          // 4 x 544 x 64
  OFFH_FWGLU   = OFFH_FW      + 544 * 256,   // 4 x 256 x 64
  OFFH_G1IH    = OFFH_FWGLU   + 256 * 256,   // 4 x 384 x 192
  OFFH_G1HH    = OFFH_G1IH    + 384 * 768,   // 4 x 256 x 192
  OFFH_G2IH    = OFFH_G1HH    + 256 * 768,
  OFFH_G2HH    = OFFH_G2IH    + 384 * 768,
  OFFH_G3IH    = OFFH_G2HH    + 256 * 768,
  OFFH_G3HH    = OFFH_G3IH    + 384 * 768,
  OFFH_GLU1    = OFFH_G3HH    + 256 * 768,
  OFFH_GLU2    = OFFH_GLU1    + 256 * 256,
  OFFH_GLU3    = OFFH_GLU2    + 256 * 256,
  OFFH_SKIP    = OFFH_GLU3    + 256 * 256,   // 4 x 1152 x 64
  OFFH_SKIPGLU = OFFH_SKIP    + 1152 * 256,
  WH_TOTAL     = OFFH_SKIPGLU + 256 * 256
};

enum : int {
  OFFC_C1  = 0,
  OFFC_C2  = OFFC_C1 + 336 * 336,
  OFFC_C3  = OFFC_C2 + 336 * 336,
  WC_TOTAL = OFFC_C3 + 336 * 512
};

__device__ __half g_wh[WH_TOTAL];
__device__ float  g_wc[WC_TOTAL];
__device__ float  g_cond[NFRAMES * NB * 512];

// ---------------------------------------------------------------------------
__global__ void transpose_k(const float* __restrict__ src, float* __restrict__ dst,
                            int O, int I) {
  int idx = blockIdx.x * blockDim.x + threadIdx.x;
  if (idx < O * I) {
    int i = idx / O;
    int o = idx % O;
    dst[idx] = src[o * I + i];
  }
}

// 4-way mode0 reorg: src[O][I] -> dst[4][Ipad][O/4] fp16
__global__ void reorg_h4(const float* __restrict__ src, __half* __restrict__ dst,
                         int O, int I, int Ipad) {
  int idx = blockIdx.x * blockDim.x + threadIdx.x;
  if (idx >= O * Ipad) return;
  int i = idx / O, o = idx % O;
  int Oq = O >> 2;
  int r = o / Oq, c = o % Oq;
  float v = (i < I) ? src[o * I + i] : 0.f;
  dst[((size_t)r * Ipad + i) * Oq + c] = __float2half(v);
}

// 4-way GRU reorg (gate-permuted): w[768][I] -> dst[4][I][192]
__global__ void reorg_gru4(const float* __restrict__ src, __half* __restrict__ dst,
                           int I) {
  int idx = blockIdx.x * blockDim.x + threadIdx.x;
  if (idx >= 768 * I) return;
  int i = idx / 768, o = idx % 768;
  int s = o & 255, g = o >> 8;
  int r = s >> 6, c = g * 64 + (s & 63);
  dst[((size_t)r * I + i) * 192 + c] = __float2half(src[o * I + i]);
}

// ---------------------------------------------------------------------------
// 2-row fp16 GEMV partial, all 32 warps = 32 K-chunks x 32 lanes (as R12).
template <int K, int NQ>
__device__ __forceinline__ void gemv2r(const __half* __restrict__ Wh,
                                       const float* __restrict__ xs, int rs,
                                       float* __restrict__ part) {
  const int tid  = threadIdx.x;
  const int kc   = tid >> 5;
  const int lane = tid & 31;
  constexpr int Kc  = K / 32;
  constexpr int NV2 = NQ / 4;
  const float2* __restrict__ W2 =
      reinterpret_cast<const float2*>(Wh) + (size_t)(kc * Kc) * NV2;

  if (NQ == 64) {
    const int row = lane >> 4, v = lane & 15;
    const float* xk = xs + row * rs + kc * Kc;
    float acc[4] = {0.f, 0.f, 0.f, 0.f};
#pragma unroll 8
    for (int k = 0; k < Kc; ++k) {
      const float xv = xk[k];
      float2 hw = W2[k * 16 + v];
      const __half2* hp = reinterpret_cast<const __half2*>(&hw);
      float2 f0 = __half22float2(hp[0]);
      float2 f1 = __half22float2(hp[1]);
      acc[0] = fmaf(xv, f0.x, acc[0]);
      acc[1] = fmaf(xv, f0.y, acc[1]);
      acc[2] = fmaf(xv, f1.x, acc[2]);
      acc[3] = fmaf(xv, f1.y, acc[3]);
    }
    float4* P4 = reinterpret_cast<float4*>(part + (row * 32 + kc) * 64);
    P4[v] = make_float4(acc[0], acc[1], acc[2], acc[3]);
  } else {  // NQ == 192
    const float* xk0 = xs + kc * Kc;
    const float* xk1 = xs + rs + kc * Kc;
    float a0[2][4], a1[2][4];
#pragma unroll
    for (int j = 0; j < 4; ++j) { a0[0][j] = a0[1][j] = a1[0][j] = a1[1][j] = 0.f; }
#pragma unroll
    for (int k = 0; k < Kc; ++k) {
      const float x0 = xk0[k], x1 = xk1[k];
      float2 hwa = W2[k * 48 + lane];
      const __half2* hpa = reinterpret_cast<const __half2*>(&hwa);
      float2 fa0 = __half22float2(hpa[0]);
      float2 fa1 = __half22float2(hpa[1]);
      a0[0][0] = fmaf(x0, fa0.x, a0[0][0]); a0[0][1] = fmaf(x0, fa0.y, a0[0][1]);
      a0[0][2] = fmaf(x0, fa1.x, a0[0][2]); a0[0][3] = fmaf(x0, fa1.y, a0[0][3]);
      a0[1][0] = fmaf(x1, fa0.x, a0[1][0]); a0[1][1] = fmaf(x1, fa0.y, a0[1][1]);
      a0[1][2] = fmaf(x1, fa1.x, a0[1][2]); a0[1][3] = fmaf(x1, fa1.y, a0[1][3]);
      if (lane < 16) {
        float2 hwb = W2[k * 48 + 32 + lane];
        const __half2* hpb = reinterpret_cast<const __half2*>(&hwb);
        float2 fb0 = __half22float2(hpb[0]);
        float2 fb1 = __half22float2(hpb[1]);
        a1[0][0] = fmaf(x0, fb0.x, a1[0][0]); a1[0][1] = fmaf(x0, fb0.y, a1[0][1]);
        a1[0][2] = fmaf(x0, fb1.x, a1[0][2]); a1[0][3] = fmaf(x0, fb1.y, a1[0][3]);
        a1[1][0] = fmaf(x1, fb0.x, a1[1][0]); a1[1][1] = fmaf(x1, fb0.y, a1[1][1]);
        a1[1][2] = fmaf(x1, fb1.x, a1[1][2]); a1[1][3] = fmaf(x1, fb1.y, a1[1][3]);
      }
    }
#pragma unroll
    for (int row = 0; row < 2; ++row) {
      float4* P4 = reinterpret_cast<float4*>(part + (row * 32 + kc) * 192);
      P4[lane] = make_float4(a0[row][0], a0[row][1], a0[row][2], a0[row][3]);
      if (lane < 16)
        P4[32 + lane] = make_float4(a1[row][0], a1[row][1], a1[row][2], a1[row][3]);
    }
  }
}

__device__ __forceinline__ float csum2r(const float* __restrict__ part, int NQ,
                                        int row, int j) {
  const float* p = part + (row * 32) * NQ + j;
  float s = 0.f;
#pragma unroll
  for (int c = 0; c < 32; c += 4) {
    float a = p[c * NQ]       + p[(c + 1) * NQ];
    float b = p[(c + 2) * NQ] + p[(c + 3) * NQ];
    s += (a + b);
  }
  return s;
}

// ---------------------------------------------------------------------------
// Phase-A gemvs on 8-warp groups (8 K-chunks each).
// fw: K=544 -> Kc=68, outputs 64 cols x 2 rows. part[(row*8+w)*64 + col].
__device__ __forceinline__ void gemv_fw8(const __half* __restrict__ Wh,
                                         const float* __restrict__ xs, int rs,
                                         float* __restrict__ part) {
  const int w = threadIdx.x >> 5;            // 0..7 (caller guards)
  const int lane = threadIdx.x & 31;
  const int row = lane >> 4, v = lane & 15;
  constexpr int Kc = 544 / 8;
  const float* xk = xs + row * rs + w * Kc;
  const float2* __restrict__ W2 =
      reinterpret_cast<const float2*>(Wh) + (size_t)(w * Kc) * 16 + v;
  float acc[4] = {0.f, 0.f, 0.f, 0.f};
#pragma unroll 8
  for (int k = 0; k < Kc; ++k) {
    const float xv = xk[k];
    float2 hw = W2[k * 16];
    const __half2* hp = reinterpret_cast<const __half2*>(&hw);
    float2 f0 = __half22float2(hp[0]);
    float2 f1 = __half22float2(hp[1]);
    acc[0] = fmaf(xv, f0.x, acc[0]);
    acc[1] = fmaf(xv, f0.y, acc[1]);
    acc[2] = fmaf(xv, f1.x, acc[2]);
    acc[3] = fmaf(xv, f1.y, acc[3]);
  }
  reinterpret_cast<float4*>(part + (row * 8 + w) * 64)[v] =
      make_float4(acc[0], acc[1], acc[2], acc[3]);
}

__device__ __forceinline__ float csum_fw8(const float* __restrict__ p,
                                          int row, int j) {
  const float* q = p + row * 8 * 64 + j;
  float a = q[0]       + q[64];
  float b = q[2 * 64]  + q[3 * 64];
  float c = q[4 * 64]  + q[5 * 64];
  float d = q[6 * 64]  + q[7 * 64];
  return (a + b) + (c + d);
}

// HH: K=256 -> Kc=32 over 8 chunks; outputs 192 cols x 2 rows.
// wg = warp index within its 8-warp group. part[(row*8+wg)*192 + col].
__device__ __forceinline__ void gemv_hh8(const __half* __restrict__ Wh,
                                         const float* __restrict__ xs,
                                         float* __restrict__ part) {
  const int wg = (threadIdx.x >> 5) & 7;
  const int lane = threadIdx.x & 31;
  constexpr int Kc = 32;
  const float* xk0 = xs + wg * Kc;
  const float* xk1 = xs + 256 + wg * Kc;
  const float2* __restrict__ W2 =
      reinterpret_cast<const float2*>(Wh) + (size_t)(wg * Kc) * 48;

  float a0[2][4], a1[2][4];
#pragma unroll
  for (int j = 0; j < 4; ++j) { a0[0][j] = a0[1][j] = a1[0][j] = a1[1][j] = 0.f; }
#pragma unroll 4
  for (int k = 0; k < Kc; ++k) {
    const float x0 = xk0[k], x1 = xk1[k];
    float2 hwa = W2[k * 48 + lane];
    const __half2* hpa = reinterpret_cast<const __half2*>(&hwa);
    float2 fa0 = __half22float2(hpa[0]);
    float2 fa1 = __half22float2(hpa[1]);
    a0[0][0] = fmaf(x0, fa0.x, a0[0][0]); a0[0][1] = fmaf(x0, fa0.y, a0[0][1]);
    a0[0][2] = fmaf(x0, fa1.x, a0[0][2]); a0[0][3] = fmaf(x0, fa1.y, a0[0][3]);
    a0[1][0] = fmaf(x1, fa0.x, a0[1][0]); a0[1][1] = fmaf(x1, fa0.y, a0[1][1]);
    a0[1][2] = fmaf(x1, fa1.x, a0[1][2]); a0[1][3] = fmaf(x1, fa1.y, a0[1][3]);
    if (lane < 16) {
      float2 hwb = W2[k * 48 + 32 + lane];
      const __half2* hpb = reinterpret_cast<const __half2*>(&hwb);
      float2 fb0 = __half22float2(hpb[0]);
      float2 fb1 = __half22float2(hpb[1]);
      a1[0][0] = fmaf(x0, fb0.x, a1[0][0]); a1[0][1] = fmaf(x0, fb0.y, a1[0][1]);
      a1[0][2] = fmaf(x0, fb1.x, a1[0][2]); a1[0][3] = fmaf(x0, fb1.y, a1[0][3]);
      a1[1][0] = fmaf(x1, fb0.x, a1[1][0]); a1[1][1] = fmaf(x1, fb0.y, a1[1][1]);
      a1[1][2] = fmaf(x1, fb1.x, a1[1][2]); a1[1][3] = fmaf(x1, fb1.y, a1[1][3]);
    }
  }
#pragma unroll
  for (int row = 0; row < 2; ++row) {
    float4* P4 = reinterpret_cast<float4*>(part + (row * 8 + wg) * 192);
    P4[lane] = make_float4(a0[row][0], a0[row][1], a0[row][2], a0[row][3]);
    if (lane < 16)
      P4[32 + lane] = make_float4(a1[row][0], a1[row][1], a1[row][2], a1[row][3]);
  }
}

__device__ __forceinline__ float csum_hh8(const float* __restrict__ p,
                                          int row, int j) {
  const float* q = p + row * 8 * 192 + j;
  float a = q[0]        + q[192];
  float b = q[2 * 192]  + q[3 * 192];
  float c = q[4 * 192]  + q[5 * 192];
  float d = q[6 * 192]  + q[7 * 192];
  return (a + b) + (c + d);
}

// ---------------------------------------------------------------------------
// conditioning net (unchanged)
__device__ __forceinline__ void gemv_part(const float* __restrict__ Wt,
                                          const float* __restrict__ xs,
                                          int K, int N, float* part) {
  const int tid = threadIdx.x;
  const int kc  = tid >> 6;
  const int g0  = tid & 63;
  const int Kc  = K >> 2;
  const int G   = N >> 2;
  const float4* __restrict__ W4 = reinterpret_cast<const float4*>(Wt) + (size_t)(kc * Kc) * G;
  const float*  __restrict__ xk = xs + kc * Kc;
  float4* P4 = reinterpret_cast<float4*>(part + kc * N);
  for (int g = g0; g < G; g += 64) {
    float4 acc = make_float4(0.f, 0.f, 0.f, 0.f);
    const float4* wp = W4 + g;
#pragma unroll 4
    for (int k = 0; k < Kc; ++k) {
      const float xv = xk[k];
      const float4 w = wp[(size_t)k * G];
      acc.x = fmaf(xv, w.x, acc.x);
      acc.y = fmaf(xv, w.y, acc.y);
      acc.z = fmaf(xv, w.z, acc.z);
      acc.w = fmaf(xv, w.w, acc.w);
    }
    P4[g] = acc;
  }
}
__device__ __forceinline__ float csum4(const float* part, int N, int j) {
  return (part[j] + part[N + j]) + (part[2 * N + j] + part[3 * N + j]);
}

__global__ __launch_bounds__(256)
void cond_kernel(const float* __restrict__ feat, const float* __restrict__ gf) {
  __shared__ __align__(16) float s_part[4 * 512];
  __shared__ float s_x[336];
  __shared__ float s_y[336];
  const int b = blockIdx.x, f = blockIdx.y, tid = threadIdx.x;

  for (int j = tid; j < 80; j += 256)  s_x[j]      = feat[(b * 80 + j) * NFRAMES + f];
  for (int j = tid; j < 256; j += 256) s_x[80 + j] = gf[b * 256 + j];
  __syncthreads();
  gemv_part(g_wc + OFFC_C1, s_x, 336, 336, s_part);
  __syncthreads();
  for (int j = tid; j < 336; j += 256) s_y[j] = tanhf(csum4(s_part, 336, j));
  __syncthreads();
  gemv_part(g_wc + OFFC_C2, s_y, 336, 336, s_part);
  __syncthreads();
  for (int j = tid; j < 336; j += 256) s_x[j] = tanhf(csum4(s_part, 336, j));
  __syncthreads();
  gemv_part(g_wc + OFFC_C3, s_x, 336, 512, s_part);
  __syncthreads();
  float* dst = g_cond + (f * NB + b) * 512;
  for (int j = tid; j < 512; j += 256) dst[j] = tanhf(csum4(s_part, 512, j));
}

// ---------------------------------------------------------------------------
// main kernel: 32 clusters of 4 CTAs; cluster q handles rows 2q, 2q+1.
extern __shared__ float s_dyn[];
#define PART_A (s_dyn)
#define PART_B (s_dyn + 2 * 32 * 192)
// phase-A sub-buffers inside PART_A region:
#define P_FW  (PART_A)                 // 2*8*64  = 1024 floats
#define P_HH1 (PART_A + 1024)          // 2*8*192 = 3072 floats
#define P_HH2 (PART_A + 4096)
#define P_HH3 (PART_A + 7168)          // ends at 10240 < 12288

__global__ __launch_bounds__(NTHREADS, 1) __cluster_dims__(4, 1, 1)
void main_kernel(const float* __restrict__ prev0,
                 const int*   __restrict__ periods,
                 const float* __restrict__ gain_w,
                 const float* __restrict__ gain_b,
                 const float* __restrict__ pg_w,
                 const float* __restrict__ pg_b,
                 const float* __restrict__ out_w,
                 float*       __restrict__ outp) {
  __shared__ float s_x[2 * 1152];
  __shared__ __align__(16) float s_xg[2 * 192];
  __shared__ __align__(16) float s_hg1[2 * 192];
  __shared__ __align__(16) float s_hg2[2 * 192];
  __shared__ __align__(16) float s_hg3[2 * 192];
  __shared__ float s_prev[2 * 256], s_s1[2 * 256], s_s2[2 * 256], s_s3[2 * 256];
  __shared__ float s_s4[2 * 260];
  __shared__ float s_fw[2 * 256], s_fw2[2 * 256];
  __shared__ float s_o1[2 * 256], s_o2[2 * 256], s_o3[2 * 256];
  __shared__ float s_sk[2 * 256], s_sk2[2 * 256];
  __shared__ float s_pl[2 * 68], s_psub[2 * 64], s_pg[2 * 4], s_gain[2 * 2];
  __shared__ float s_out[2 * 64];

  const int tid  = threadIdx.x;
  const int rank = blockIdx.x & 3;
  const int q    = blockIdx.x >> 2;

  auto exch = [&](float* addr, float v) {
    *addr = v;
    uint32_t a = s2u_(addr);
    st_peer_(mapa_u_(a, (rank + 1) & 3), v);
    st_peer_(mapa_u_(a, (rank + 2) & 3), v);
    st_peer_(mapa_u_(a, (rank + 3) & 3), v);
  };

  if (tid < 512) {
    s_prev[tid] = prev0[q * 512 + tid];
    s_s1[tid] = 0.f; s_s2[tid] = 0.f; s_s3[tid] = 0.f;
  }
  if (tid < 520) s_s4[tid] = 0.f;
  __syncthreads();

  const float gb0 = gain_b[0];
  int per[2];
  const float* condr[2];

  for (int f = 0; f < NFRAMES; ++f) {
    per[0] = periods[(q * 2 + 0) * NFRAMES + f];
    per[1] = periods[(q * 2 + 1) * NFRAMES + f];
    condr[0] = g_cond + (f * NB + q * 2 + 0) * 512;
    condr[1] = g_cond + (f * NB + q * 2 + 1) * 512;

    for (int i = 0; i < 4; ++i) {
      // ---- gain: warp r computes row r
      if (tid < 64) {
        int row = tid >> 5, l = tid & 31;
        const float* sf = condr[row] + i * 128;
        float d = 0.f;
        for (int k = l; k < 128; k += 32) d = fmaf(sf[k], gain_w[k], d);
#pragma unroll
        for (int o = 16; o; o >>= 1) d += __shfl_xor_sync(0xffffffffu, d, o);
        if (l == 0) {
          float g = expf(d + gb0);
          s_gain[row * 2]     = g;
          s_gain[row * 2 + 1] = 1.0f / (1e-5f + g);
        }
      }
      __syncthreads();

      // ---- pitch gather + psub per row
      if (tid < 136) {
        int row = tid / 68, t = tid % 68;
        int idx = 256 - per[row] + t - 2;
        if (idx >= 256) idx -= per[row];
        s_pl[row * 68 + t] = s_prev[row * 256 + idx] * s_gain[row * 2 + 1];
      } else if (tid >= 256 && tid < 384) {
        int row = (tid - 256) >> 6, t = (tid - 256) & 63;
        s_psub[row * 64 + t] = s_prev[row * 256 + 192 + t] * s_gain[row * 2 + 1];
      }
      __syncthreads();

      // ---- fw input assembly: per row [sf(128), psub(64), pl(68), s4(260), pad]
      for (int idx = tid; idx < 2 * 544; idx += NTHREADS) {
        int row = idx / 544, p = idx % 544;
        float v;
        if (p < 128)       v = condr[row][i * 128 + p];
        else if (p < 192)  v = s_psub[row * 64 + (p - 128)];
        else if (p < 260)  v = s_pl[row * 68 + (p - 192)];
        else if (p < 520)  v = s_s4[row * 260 + (p - 260)];
        else               v = 0.f;
        s_x[row * 1152 + p] = v;
      }
      __syncthreads();
      // s4 <- sif (x[0:260]); stable during gemv
      if (tid < 520) {
        int row = tid / 260, t = tid % 260;
        s_s4[row * 260 + t] = s_x[row * 1152 + t];
      }

      // ======= PHASE A: fw + HH1 + HH2 + HH3 on disjoint warp groups =======
      {
        const int w = tid >> 5;
        if (w < 8)       gemv_fw8(g_wh + OFFH_FW + rank * 544 * 64, s_x, 1152, P_FW);
        else if (w < 16) gemv_hh8(g_wh + OFFH_G1HH + rank * 256 * 192, s_s1, P_HH1);
        else if (w < 24) gemv_hh8(g_wh + OFFH_G2HH + rank * 256 * 192, s_s2, P_HH2);
        else             gemv_hh8(g_wh + OFFH_G3HH + rank * 256 * 192, s_s3, P_HH3);
      }
      __syncthreads();
      if (tid < 128) {
        int row = tid >> 6, jl = tid & 63;
        exch(&s_fw[row * 256 + rank * 64 + jl], tanhf(csum_fw8(P_FW, row, jl)));
      }
      for (int idx = tid; idx < 3 * 384; idx += NTHREADS) {
        int m = idx / 384, t = idx % 384;
        int row = t / 192, c = t % 192;
        float* dst = (m == 0) ? s_hg1 : (m == 1) ? s_hg2 : s_hg3;
        const float* src = (m == 0) ? P_HH1 : (m == 1) ? P_HH2 : P_HH3;
        dst[row * 192 + c] = csum_hh8(src, row, c);
      }
      CLUSTER_SYNC_();

      gemv2r<256, 64>(g_wh + OFFH_FWGLU + rank * 256 * 64, s_fw, 256, PART_A);
      __syncthreads();
      if (tid < 128) {
        int row = tid >> 6, jl = tid & 63;
        int j = rank * 64 + jl;
        float v = s_fw[row * 256 + j] * sigmoidf_(csum2r(PART_A, 64, row, jl));
        exch(&s_fw2[row * 256 + j], v);
      }
      CLUSTER_SYNC_();

      // ---- pg: 8 warps (row, gate) redundant per CTA
      if (tid < 256) {
        int w = tid >> 5, l = tid & 31;
        int row = w >> 2, g = w & 3;
        float d = 0.f;
        for (int k = l; k < 256; k += 32)
          d = fmaf(s_fw2[row * 256 + k], pg_w[g * 256 + k], d);
#pragma unroll
        for (int o = 16; o; o >>= 1) d += __shfl_xor_sync(0xffffffffu, d, o);
        if (l == 0) s_pg[row * 4 + g] = sigmoidf_(d + pg_b[g]) + 1e-5f;
      }
      __syncthreads();

      // ================= GRU (IH-only) + GLU macros =================
#define GRU_STAGE(SRC, OFF_IH, HG, SSTATE, PGI)                                  \
      for (int idx = tid; idx < 2 * 384; idx += NTHREADS) {                      \
        int row = idx / 384, p = idx % 384;                                      \
        float v;                                                                 \
        if (p < 256)       v = SRC[row * 256 + p];                               \
        else if (p < 320)  v = s_pg[row * 4 + PGI] * s_pl[row * 68 + 2 + (p - 256)]; \
        else               v = s_psub[row * 64 + (p - 320)];                     \
        s_x[row * 1152 + p] = v;                                                 \
      }                                                                          \
      __syncthreads();                                                           \
      gemv2r<384, 192>(g_wh + OFF_IH + rank * 384 * 192, s_x, 1152, PART_A);     \
      __syncthreads();                                                           \
      if (tid < 96) {                                                            \
        int row = tid / 48, g4 = tid % 48;                                       \
        const float* p = PART_A + row * 32 * 192 + g4 * 4;                       \
        float4 u0 = make_float4(0.f, 0.f, 0.f, 0.f);                             \
        float4 u1 = make_float4(0.f, 0.f, 0.f, 0.f);                             \
        _Pragma("unroll")                                                        \
        for (int c = 0; c < 32; c += 2) {                                        \
          float4 va = *reinterpret_cast<const float4*>(p + c * 192);             \
          float4 vb = *reinterpret_cast<const float4*>(p + (c + 1) * 192);       \
          u0.x += va.x; u0.y += va.y; u0.z += va.z; u0.w += va.w;                \
          u1.x += vb.x; u1.y += vb.y; u1.z += vb.z; u1.w += vb.w;                \
        }                                                                        \
        float4 s = make_float4(u0.x + u1.x, u0.y + u1.y, u0.z + u1.z, u0.w + u1.w); \
        *reinterpret_cast<float4*>(s_xg + row * 192 + g4 * 4) = s;               \
      }                                                                          \
      __syncthreads();                                                           \
      if (tid < 128) {                                                           \
        int row = tid >> 6, sl = tid & 63;                                       \
        float r = sigmoidf_(s_xg[row * 192 + sl]       + HG[row * 192 + sl]);    \
        float z = sigmoidf_(s_xg[row * 192 + 64 + sl]  + HG[row * 192 + 64 + sl]); \
        float n = tanhf(s_xg[row * 192 + 128 + sl] + r * HG[row * 192 + 128 + sl]); \
        int j = rank * 64 + sl;                                                  \
        float v = (1.f - z) * n + z * SSTATE[row * 256 + j];                     \
        exch(&SSTATE[row * 256 + j], v);                                         \
      }                                                                          \
      CLUSTER_SYNC_();

#define GLU_STAGE(OFF_GLU, SSTATE, DST)                                          \
      gemv2r<256, 64>(g_wh + OFF_GLU + rank * 256 * 64, SSTATE, 256, PART_A);    \
      __syncthreads();                                                           \
      if (tid < 128) {                                                           \
        int row = tid >> 6, jl = tid & 63;                                       \
        int j = rank * 64 + jl;                                                  \
        float v = SSTATE[row * 256 + j] * sigmoidf_(csum2r(PART_A, 64, row, jl)); \
        exch(&DST[row * 256 + j], v);                                            \
      }                                                                          \
      CLUSTER_SYNC_();

      GRU_STAGE(s_fw2, OFFH_G1IH, s_hg1, s_s1, 0)
      GLU_STAGE(OFFH_GLU1, s_s1, s_o1)
      GRU_STAGE(s_o1, OFFH_G2IH, s_hg2, s_s2, 1)
      GLU_STAGE(OFFH_GLU2, s_s2, s_o2)
      GRU_STAGE(s_o2, OFFH_G3IH, s_hg3, s_s3, 2)
      GLU_STAGE(OFFH_GLU3, s_s3, s_o3)
#undef GRU_STAGE
#undef GLU_STAGE

      // ---- skip input: per row [o1,o2,o3,fw2,pg3*pl2,psub] = 1152
      for (int idx = tid; idx < 2 * 1152; idx += NTHREADS) {
        int row = idx / 1152, p = idx % 1152;
        float v;
        if (p < 256)        v = s_o1[row * 256 + p];
        else if (p < 512)   v = s_o2[row * 256 + (p - 256)];
        else if (p < 768)   v = s_o3[row * 256 + (p - 512)];
        else if (p < 1024)  v = s_fw2[row * 256 + (p - 768)];
        else if (p < 1088)  v = s_pg[row * 4 + 3] * s_pl[row * 68 + 2 + (p - 1024)];
        else                v = s_psub[row * 64 + (p - 1088)];
        s_x[row * 1152 + p] = v;
      }
      __syncthreads();
      gemv2r<1152, 64>(g_wh + OFFH_SKIP + rank * 1152 * 64, s_x, 1152, PART_A);
      __syncthreads();
      if (tid < 128) {
        int row = tid >> 6, jl = tid & 63;
        exch(&s_sk[row * 256 + rank * 64 + jl], tanhf(csum2r(PART_A, 64, row, jl)));
      }
      CLUSTER_SYNC_();

      gemv2r<256, 64>(g_wh + OFFH_SKIPGLU + rank * 256 * 64, s_sk, 256, PART_A);
      __syncthreads();
      if (tid < 128) {
        int row = tid >> 6, jl = tid & 63;
        int j = rank * 64 + jl;
        float v = s_sk[row * 256 + j] * sigmoidf_(csum2r(PART_A, 64, row, jl));
        exch(&s_sk2[row * 256 + j], v);
      }
      CLUSTER_SYNC_();

      // ---- out: warp w -> output o = rank*16 + (w>>1), row = w&1
      {
        const int w = tid >> 5, l = tid & 31;
        const int o = rank * 16 + (w >> 1), row = w & 1;
        const float4* wr = reinterpret_cast<const float4*>(out_w + o * 256) + l * 2;
        const float4* xr = reinterpret_cast<const float4*>(s_sk2 + row * 256) + l * 2;
        float4 wa = wr[0], wb = wr[1];
        float4 xa = xr[0], xb = xr[1];
        float d = wa.x * xa.x + wa.y * xa.y + wa.z * xa.z + wa.w * xa.w
                + wb.x * xb.x + wb.y * xb.y + wb.z * xb.z + wb.w * xb.w;
#pragma unroll
        for (int oo = 16; oo; oo >>= 1) d += __shfl_xor_sync(0xffffffffu, d, oo);
        if (l == 0) {
          float v = tanhf(d) * s_gain[row * 2];
          exch(&s_out[row * 64 + o], v);
          outp[(q * 2 + row) * 25600 + f * 256 + i * 64 + o] = v;
        }
      }
      CLUSTER_SYNC_();

      // ---- prev = [prev[64:], out] per row
      float pv = 0.f;
      if (tid < 512) {
        int row = tid >> 8, t = tid & 255;
        pv = (t < 192) ? s_prev[row * 256 + t + 64] : s_out[row * 64 + (t - 192)];
      }
      __syncthreads();
      if (tid < 512) s_prev[tid] = pv;
      __syncthreads();
    }
  }
}

// ---------------------------------------------------------------------------
extern "C" void kernel_launch(void* const* d_in, const int* in_sizes, int n_in,
                              void* d_out, int out_size) {
  (void)in_sizes; (void)n_in; (void)out_size;
  const float* features = (const float*)d_in[0];
  const float* gfeat    = (const float*)d_in[1];
  const float* prev     = (const float*)d_in[2];
  const int*   periods  = (const int*)d_in[3];
  const float* cond_w1  = (const float*)d_in[4];
  const float* cond_w2  = (const float*)d_in[5];
  const float* cond_w3  = (const float*)d_in[6];
  const float* gain_w   = (const float*)d_in[7];
  const float* gain_b   = (const float*)d_in[8];
  const float* fw_w     = (const float*)d_in[9];
  const float* fw_glu_w = (const float*)d_in[10];
  const float* pg_w     = (const float*)d_in[11];
  const float* pg_b     = (const float*)d_in[12];
  const float* g1ih     = (const float*)d_in[13];
  const float* g1hh     = (const float*)d_in[14];
  const float* g2ih     = (const float*)d_in[15];
  const float* g2hh     = (const float*)d_in[16];
  const float* g3ih     = (const float*)d_in[17];
  const float* g3hh     = (const float*)d_in[18];
  const float* glu1     = (const float*)d_in[19];
  const float* glu2     = (const float*)d_in[20];
  const float* glu3     = (const float*)d_in[21];
  const float* skip_w   = (const float*)d_in[22];
  const float* skipglu  = (const float*)d_in[23];
  const float* out_w    = (const float*)d_in[24];

  __half* wh = nullptr;
  float*  wc = nullptr;
  cudaGetSymbolAddress((void**)&wh, g_wh);
  cudaGetSymbolAddress((void**)&wc, g_wc);

  auto rg4 = [&](const float* src, int off, int O, int I, int Ipad) {
    int tot = O * Ipad;
    reorg_h4<<<(tot + 255) / 256, 256>>>(src, wh + off, O, I, Ipad);
  };
  auto rgg = [&](const float* src, int off, int I) {
    int tot = 768 * I;
    reorg_gru4<<<(tot + 255) / 256, 256>>>(src, wh + off, I);
  };
  auto tpc = [&](const float* src, int off, int O, int I) {
    int tot = O * I;
    transpose_k<<<(tot + 255) / 256, 256>>>(src, wc + off, O, I);
  };

  rg4(fw_w,     OFFH_FW,      256, 520, 544);
  rg4(fw_glu_w, OFFH_FWGLU,   256, 256, 256);
  rgg(g1ih,     OFFH_G1IH,    384);
  rgg(g1hh,     OFFH_G1HH,    256);
  rgg(g2ih,     OFFH_G2IH,    384);
  rgg(g2hh,     OFFH_G2HH,    256);
  rgg(g3ih,     OFFH_G3IH,    384);
  rgg(g3hh,     OFFH_G3HH,    256);
  rg4(glu1,     OFFH_GLU1,    256, 256, 256);
  rg4(glu2,     OFFH_GLU2,    256, 256, 256);
  rg4(glu3,     OFFH_GLU3,    256, 256, 256);
  rg4(skip_w,   OFFH_SKIP,    256, 1152, 1152);
  rg4(skipglu,  OFFH_SKIPGLU, 256, 256, 256);
  tpc(cond_w1,  OFFC_C1,      336, 336);
  tpc(cond_w2,  OFFC_C2,      336, 336);
  tpc(cond_w3,  OFFC_C3,      512, 336);

  dim3 cg(NB, NFRAMES);
  cond_kernel<<<cg, 256>>>(features, gfeat);

  const int dyn_smem = 2 * 2 * 32 * 192 * (int)sizeof(float);  // 96 KB
  cudaFuncSetAttribute(main_kernel, cudaFuncAttributeMaxDynamicSharedMemorySize, dyn_smem);
  main_kernel<<<128, NTHREADS, dyn_smem>>>(prev, periods, gain_w, gain_b,
                                           pg_w, pg_b, out_w, (float*)d_out);
}